// round 10
// baseline (speedup 1.0000x reference)
#include <cuda_runtime.h>
#include <cuda_bf16.h>
#include <cuda_fp16.h>
#include <math.h>
#include <stdint.h>

// ---------------- problem constants ----------------
#define B_   2
#define S_   2048
#define HID  2048
#define HKq  16
#define HVv  32
#define DKd  128
#define DVd  128
#define KC   4
#define CHUNK 64
#define NCH  (S_/CHUNK)          // 32
#define KEY_DIM 2048
#define VALUE_DIM 4096
#define CONV_DIM 8192
#define QKVZ_N 12288
#define BSz  (B_*S_)             // 4096
#define QSCALE 0.08838834764831845f   // DK^-0.5
#define SW 132                   // float4-aligned, conflict-free smem row stride

// ---------------- scratch (static device memory; no allocations) ------------
__device__ float g_qkvz[(size_t)BSz*QKVZ_N];               // [BS,12288] q|k|v|z
__device__ float g_bap[(size_t)8*BSz*64];                  // split-K partials
__device__ float g_q[(size_t)B_*HKq*S_*DKd];
__device__ float g_k[(size_t)B_*HKq*S_*DKd];
__device__ float g_v[(size_t)B_*HVv*S_*DVd];
__device__ float g_g[(size_t)B_*HVv*S_];
__device__ float g_beta[(size_t)B_*HVv*S_];
__device__ float g_gc[(size_t)B_*HVv*S_];
__device__ float g_vadj[(size_t)B_*HVv*S_*DVd];
__device__ float g_kcd[(size_t)B_*HVv*S_*DKd];
__device__ float g_attn[(size_t)B_*HVv*S_*CHUNK];
__device__ float g_o[(size_t)BSz*VALUE_DIM];

// fp16 operand buffers
__device__ __half g_p [(size_t)8388608];    // A1 (hidden) / B2t (Wout^T)
__device__ __half g_r [(size_t)25165824];   // B1t (Wqkvz^T) ; later A2 (gated_norm out)

__device__ __forceinline__ uint32_t smem_u32(const void* p) {
    uint32_t a;
    asm("{ .reg .u64 t; cvta.to.shared.u64 t, %1; cvt.u32.u64 %0, t; }" : "=r"(a) : "l"(p));
    return a;
}

// ---------------- fp32 -> fp16 (elementwise, float4) ----------------
__global__ void cvt_h(const float* __restrict__ X, __half* __restrict__ H) {
    size_t i = ((size_t)blockIdx.x * 256 + threadIdx.x) * 4;
    float4 v = *(const float4*)&X[i];
    __half2 h0 = __floats2half2_rn(v.x, v.y);
    __half2 h1 = __floats2half2_rn(v.z, v.w);
    uint2 hv;
    hv.x = *(uint32_t*)&h0; hv.y = *(uint32_t*)&h1;
    *(uint2*)&H[i] = hv;
}

// ---------------- fp32 [K,N] -> fp16 [N,K] transpose ----------------
__global__ void cvt_T(const float* __restrict__ W, __half* __restrict__ Ht, int K, int N) {
    __shared__ float tile[32][33];
    int n0 = blockIdx.x * 32, k0 = blockIdx.y * 32;
    int tx = threadIdx.x, ty = threadIdx.y;   // 32 x 8
#pragma unroll
    for (int j = 0; j < 32; j += 8)
        tile[ty + j][tx] = W[(size_t)(k0 + ty + j) * N + n0 + tx];
    __syncthreads();
#pragma unroll
    for (int j = 0; j < 32; j += 8)
        Ht[(size_t)(n0 + ty + j) * K + k0 + tx] = __float2half_rn(tile[tx][ty + j]);
}

// ============ fp16 HMMA GEMM: C[M,N] = A[M,K] @ Bt[N,K]^T ============
// FACC=0: fp32-accum mma. FACC=1: fp16-accum mma per K=16 chunk, immediately
// widened and added into fp32 registers (no fp16 running sums).
#define PSH 40
#define TEN2 (128*PSH)
#define STG1 (2*TEN2)
#define NSTG 4

__device__ __forceinline__ void mma_f16(float* c, const uint32_t* a, const uint32_t* b) {
    asm volatile("mma.sync.aligned.m16n8k16.row.col.f32.f16.f16.f32 "
                 "{%0,%1,%2,%3}, {%4,%5,%6,%7}, {%8,%9}, {%0,%1,%2,%3};"
                 : "+f"(c[0]), "+f"(c[1]), "+f"(c[2]), "+f"(c[3])
                 : "r"(a[0]), "r"(a[1]), "r"(a[2]), "r"(a[3]), "r"(b[0]), "r"(b[1]));
}
__device__ __forceinline__ void mma_f16acc(float* c, const uint32_t* a, const uint32_t* b) {
    uint32_t d0, d1;
    asm volatile("mma.sync.aligned.m16n8k16.row.col.f16.f16.f16.f16 "
                 "{%0,%1}, {%2,%3,%4,%5}, {%6,%7}, {%8,%8};"
                 : "=r"(d0), "=r"(d1)
                 : "r"(a[0]), "r"(a[1]), "r"(a[2]), "r"(a[3]),
                   "r"(b[0]), "r"(b[1]), "r"(0u));
    __half2 h0 = *reinterpret_cast<__half2*>(&d0);
    __half2 h1 = *reinterpret_cast<__half2*>(&d1);
    float2 f0 = __half22float2(h0);
    float2 f1 = __half22float2(h1);
    c[0] += f0.x; c[1] += f0.y; c[2] += f1.x; c[3] += f1.y;
}
__device__ __forceinline__ void ldmx4(uint32_t* r, uint32_t addr) {
    asm volatile("ldmatrix.sync.aligned.m8n8.x4.shared.b16 {%0,%1,%2,%3}, [%4];"
                 : "=r"(r[0]), "=r"(r[1]), "=r"(r[2]), "=r"(r[3]) : "r"(addr));
}

__device__ __forceinline__ void stage_load(uint32_t sbase_b, int stage,
    const __half* a0, const __half* b0, int K, int kt, int tid)
{
    const __half* gp[2] = {a0, b0};
    uint32_t st_b = sbase_b + (uint32_t)stage * (STG1 * 2);
#pragma unroll
    for (int t = 0; t < 2; t++) {
        uint32_t tb = st_b + (uint32_t)t * (TEN2 * 2);
#pragma unroll
        for (int j = 0; j < 2; j++) {
            int idx = j * 256 + tid;
            int row = idx >> 2, c16 = idx & 3;
            uint32_t sa = tb + (uint32_t)(row * (PSH*2) + c16 * 16);
            const void* ga = gp[t] + (size_t)row * K + (size_t)kt * 32 + c16 * 8;
            asm volatile("cp.async.cg.shared.global [%0], [%1], 16;" :: "r"(sa), "l"(ga));
        }
    }
    asm volatile("cp.async.commit_group;" ::: "memory");
}

template<int FACC>
__global__ void __launch_bounds__(256, 2) mmgemm(
    const __half* __restrict__ Ah, const __half* __restrict__ Bh,
    float* __restrict__ C, int M, int N, int K)
{
    extern __shared__ __half smem[];
    uint32_t sbase = smem_u32(smem);
    int tid = threadIdx.x, lane = tid & 31, wid = tid >> 5;
    int warpM = wid >> 2, warpN = wid & 3;
    int bm = blockIdx.x, bn = blockIdx.y;
    const int T = K >> 5;

    const __half* a0 = Ah + (size_t)bm * 128 * K;
    const __half* b0 = Bh + (size_t)bn * 128 * K;

    int g = lane >> 3, lr = lane & 7;
    uint32_t aoff = (uint32_t)((warpM*64 + (g&1)*8 + lr) * PSH + (g>>1)*8);
    uint32_t boff = (uint32_t)((warpN*32 + (g>>1)*8 + lr) * PSH + (g&1)*8);

    float acc[4][4][4];
#pragma unroll
    for (int i = 0; i < 4; i++)
#pragma unroll
        for (int j = 0; j < 4; j++)
#pragma unroll
            for (int r = 0; r < 4; r++) acc[i][j][r] = 0.f;

    stage_load(sbase, 0, a0, b0, K, 0, tid);
    stage_load(sbase, 1, a0, b0, K, 1, tid);
    stage_load(sbase, 2, a0, b0, K, 2, tid);

    for (int kt = 0; kt < T; kt++) {
        int rem = T - 1 - kt;
        if (rem >= 2)      asm volatile("cp.async.wait_group 2;" ::: "memory");
        else if (rem == 1) asm volatile("cp.async.wait_group 1;" ::: "memory");
        else               asm volatile("cp.async.wait_group 0;" ::: "memory");
        __syncthreads();
        if (kt + 3 < T) stage_load(sbase, (kt + 3) % NSTG, a0, b0, K, kt + 3, tid);

        uint32_t st = sbase + (uint32_t)(kt % NSTG) * (STG1 * 2);
        uint32_t sA = st, sB = st + TEN2*2;
#pragma unroll
        for (int ks = 0; ks < 2; ks++) {
            int kk = ks * 16;
            uint32_t ah[4][4], bh[4][2];
#pragma unroll
            for (int mi = 0; mi < 4; mi++)
                ldmx4(ah[mi], sA + (aoff + mi*16*PSH + kk) * 2);
#pragma unroll
            for (int p = 0; p < 2; p++) {
                uint32_t rh[4];
                ldmx4(rh, sB + (boff + p*16*PSH + kk) * 2);
                bh[2*p][0] = rh[0]; bh[2*p][1] = rh[1];
                bh[2*p+1][0] = rh[2]; bh[2*p+1][1] = rh[3];
            }
#pragma unroll
            for (int mi = 0; mi < 4; mi++)
#pragma unroll
                for (int ni = 0; ni < 4; ni++) {
                    if (FACC) mma_f16acc(acc[mi][ni], ah[mi], bh[ni]);
                    else      mma_f16   (acc[mi][ni], ah[mi], bh[ni]);
                }
        }
        __syncthreads();
    }

    int rr = lane >> 2, cc = (lane & 3) * 2;
#pragma unroll
    for (int mi = 0; mi < 4; mi++) {
        int row0 = bm * 128 + warpM * 64 + mi * 16 + rr;
#pragma unroll
        for (int ni = 0; ni < 4; ni++) {
            int col = bn * 128 + warpN * 32 + ni * 8 + cc;
            float2 v0 = make_float2(acc[mi][ni][0], acc[mi][ni][1]);
            float2 v1 = make_float2(acc[mi][ni][2], acc[mi][ni][3]);
            *(float2*)&C[(size_t)row0 * N + col]       = v0;
            *(float2*)&C[(size_t)(row0 + 8) * N + col] = v1;
        }
    }
}

// ------------- BA projection split-K -> partials -------------
__global__ void gemm_ba_part(const float* __restrict__ X, const float* __restrict__ W) {
    __shared__ float Xs[64][65];
    __shared__ float Ws[64][64];
    int tid = threadIdx.x;
    int row0 = blockIdx.x * 64;
    int kbase = blockIdx.y * 256;
    int col = (tid & 15) * 4;
    int r0 = (tid >> 4) * 4;
    float acc[4][4] = {};
    for (int k0 = kbase; k0 < kbase + 256; k0 += 64) {
#pragma unroll
        for (int j = 0; j < 16; j++) {
            int idx = j * 256 + tid;
            int r = idx >> 6, kk = idx & 63;
            Xs[r][kk] = X[(size_t)(row0 + r) * HID + k0 + kk];
        }
#pragma unroll
        for (int j = 0; j < 16; j++) {
            int idx = j * 256 + tid;
            int kk = idx >> 6, c = idx & 63;
            Ws[kk][c] = W[(size_t)(k0 + kk) * 64 + c];
        }
        __syncthreads();
#pragma unroll 8
        for (int kk = 0; kk < 64; kk++) {
            float4 b = *(float4*)&Ws[kk][col];
#pragma unroll
            for (int r = 0; r < 4; r++) {
                float a = Xs[r0 + r][kk];
                acc[r][0] += a*b.x; acc[r][1] += a*b.y; acc[r][2] += a*b.z; acc[r][3] += a*b.w;
            }
        }
        __syncthreads();
    }
    float* dst = g_bap + (size_t)blockIdx.y * BSz * 64;
#pragma unroll
    for (int r = 0; r < 4; r++)
        *(float4*)&dst[(size_t)(row0 + r0 + r) * 64 + col] =
            make_float4(acc[r][0], acc[r][1], acc[r][2], acc[r][3]);
}

// -------- conv + silu + l2norm + head transpose + gates (+ba reduce fused) --------
__global__ void conv_gate(const float* __restrict__ cw, const float* __restrict__ dtb,
                          const float* __restrict__ Alog) {
    int bs = blockIdx.x;
    int b = bs / S_, s = bs % S_;
    int tid = threadIdx.x;
    __shared__ float cs[CONV_DIM];
    __shared__ float hsum[32];
    const float* base = g_qkvz + (size_t)bs * QKVZ_N;

    for (int c = tid; c < CONV_DIM; c += 256) {
        float w0 = cw[c*4+0], w1 = cw[c*4+1], w2 = cw[c*4+2], w3 = cw[c*4+3];
        float acc = base[c] * w3;
        if (s >= 1) acc += base[c - (size_t)QKVZ_N] * w2;
        if (s >= 2) acc += base[c - (size_t)2*QKVZ_N] * w1;
        if (s >= 3) acc += base[c - (size_t)3*QKVZ_N] * w0;
        cs[c] = acc / (1.f + __expf(-acc));
    }
    __syncthreads();
    int warp = tid >> 5, lane = tid & 31;
    for (int h = warp; h < 32; h += 8) {
        float ss = 0.f;
        for (int d = lane; d < 128; d += 32) { float v = cs[h*128 + d]; ss += v * v; }
#pragma unroll
        for (int o = 16; o; o >>= 1) ss += __shfl_xor_sync(~0u, ss, o);
        if (!lane) hsum[h] = rsqrtf(ss + 1e-6f);
    }
    __syncthreads();
    for (int c = tid; c < KEY_DIM; c += 256) {
        int h = c >> 7, d = c & 127;
        g_q[(((size_t)b*HKq + h)*S_ + s)*DKd + d] = cs[c] * hsum[h] * QSCALE;
    }
    for (int c = tid; c < KEY_DIM; c += 256) {
        int h = c >> 7, d = c & 127;
        g_k[(((size_t)b*HKq + h)*S_ + s)*DKd + d] = cs[KEY_DIM + c] * hsum[16 + h];
    }
    for (int c = tid; c < VALUE_DIM; c += 256) {
        int h = c >> 7, d = c & 127;
        g_v[(((size_t)b*HVv + h)*S_ + s)*DVd + d] = cs[2*KEY_DIM + c];
    }
    if (tid < 64) {
        float bb = 0.f;
#pragma unroll
        for (int p = 0; p < 8; p++) bb += g_bap[(size_t)p * BSz * 64 + (size_t)bs * 64 + tid];
        if (tid < 32) {
            g_beta[((size_t)b*HVv + tid)*S_ + s] = 1.f / (1.f + expf(-bb));
        } else {
            int h = tid - 32;
            float a = bb + dtb[h];
            float sp = (a > 20.f) ? a : log1pf(expf(a));
            g_g[((size_t)b*HVv + h)*S_ + s] = -expf(Alog[h]) * sp;
        }
    }
}

// -------- per-(b,h,chunk) intra-chunk quantities (register-tiled float4) --------
__global__ void __launch_bounds__(256, 1) chunk_prep() {
    extern __shared__ float sm[];
    float* q_s  = sm;
    float* k_s  = q_s  + 64*SW;
    float* vb_s = k_s  + 64*SW;
    float* A_s  = vb_s + 64*SW;
    float* T_s  = A_s  + 64*64;
    __shared__ float gc_s[64], beta_s[64], kbe_s[64];

    int blk = blockIdx.x;
    int n = blk & 31, h = (blk >> 5) & 31, b = blk >> 10;
    int hq = h >> 1;
    int tid = threadIdx.x;

    size_t qk_off = (((size_t)b*HKq + hq)*S_ + (size_t)n*CHUNK) * DKd;
    size_t v_off  = (((size_t)b*HVv + h )*S_ + (size_t)n*CHUNK) * DVd;
    size_t gb_off = ((size_t)b*HVv + h)*S_ + (size_t)n*CHUNK;

    if (tid < 64) { gc_s[tid] = g_g[gb_off + tid]; beta_s[tid] = g_beta[gb_off + tid]; }
    __syncthreads();
    if (tid == 0) { for (int i = 1; i < 64; i++) gc_s[i] += gc_s[i - 1]; }
    __syncthreads();
    if (tid < 64) {
        g_gc[gb_off + tid] = gc_s[tid];
        kbe_s[tid] = beta_s[tid] * expf(gc_s[tid]);
    }
    for (int idx = tid; idx < 2048; idx += 256) {
        int r = idx >> 5, d = (idx & 31) * 4;
        float4 qv = *(const float4*)&g_q[qk_off + (size_t)r*128 + d];
        float4 kv = *(const float4*)&g_k[qk_off + (size_t)r*128 + d];
        float4 vv = *(const float4*)&g_v[v_off  + (size_t)r*128 + d];
        float be = beta_s[r];
        vv.x *= be; vv.y *= be; vv.z *= be; vv.w *= be;
        *(float4*)&q_s [r*SW + d] = qv;
        *(float4*)&k_s [r*SW + d] = kv;
        *(float4*)&vb_s[r*SW + d] = vv;
    }
    __syncthreads();

    {
        int jt = tid & 15, ct = tid >> 4;
        int j0 = jt * 4, c0 = ct * 4;
        float aa[4][4] = {}, aq[4][4] = {};
        for (int dk = 0; dk < 128; dk += 4) {
            float4 kj[4], kc[4], qc[4];
#pragma unroll
            for (int x = 0; x < 4; x++) kj[x] = *(float4*)&k_s[(j0+x)*SW + dk];
#pragma unroll
            for (int x = 0; x < 4; x++) kc[x] = *(float4*)&k_s[(c0+x)*SW + dk];
#pragma unroll
            for (int x = 0; x < 4; x++) qc[x] = *(float4*)&q_s[(c0+x)*SW + dk];
#pragma unroll
            for (int ci = 0; ci < 4; ci++)
#pragma unroll
                for (int ji = 0; ji < 4; ji++) {
                    aa[ci][ji] += kc[ci].x*kj[ji].x + kc[ci].y*kj[ji].y
                                + kc[ci].z*kj[ji].z + kc[ci].w*kj[ji].w;
                    aq[ci][ji] += qc[ci].x*kj[ji].x + qc[ci].y*kj[ji].y
                                + qc[ci].z*kj[ji].z + qc[ci].w*kj[ji].w;
                }
        }
        size_t at_off = gb_off * CHUNK;
#pragma unroll
        for (int ci = 0; ci < 4; ci++)
#pragma unroll
            for (int ji = 0; ji < 4; ji++) {
                int c = c0 + ci, j = j0 + ji;
                float e = __expf(gc_s[c] - gc_s[j]);
                A_s[c*64 + j] = (j < c) ? aa[ci][ji] * beta_s[c] * e : 0.f;
                g_attn[at_off + c*64 + j] = (j <= c) ? aq[ci][ji] * e : 0.f;
            }
    }
    __syncthreads();

    if (tid < 64) {
        int col = tid;
        for (int c = 0; c < 64; c++) {
            float ssum = (c == col) ? 1.f : 0.f;
            for (int j = col; j < c; j++) ssum -= A_s[c*64 + j] * T_s[j*65 + col];
            T_s[c*65 + col] = (c >= col) ? ssum : 0.f;
        }
    }
    __syncthreads();

    {
        int ct8 = tid >> 5, lane = tid & 31;
        int c0 = ct8 * 8, d0 = lane * 4;
        float av[8][4] = {}, ak[8][4] = {};
        int jmax = c0 + 8;
        for (int j = 0; j < jmax; j++) {
            float4 vv = *(float4*)&vb_s[j*SW + d0];
            float4 kk = *(float4*)&k_s [j*SW + d0];
            float kb = kbe_s[j];
            kk.x *= kb; kk.y *= kb; kk.z *= kb; kk.w *= kb;
#pragma unroll
            for (int ci = 0; ci < 8; ci++) {
                float t = T_s[(c0+ci)*65 + j];
                av[ci][0] += t*vv.x; av[ci][1] += t*vv.y; av[ci][2] += t*vv.z; av[ci][3] += t*vv.w;
                ak[ci][0] += t*kk.x; ak[ci][1] += t*kk.y; ak[ci][2] += t*kk.z; ak[ci][3] += t*kk.w;
            }
        }
        size_t kcd_off = (((size_t)b*HVv + h)*S_ + (size_t)n*CHUNK) * DKd;
#pragma unroll
        for (int ci = 0; ci < 8; ci++) {
            *(float4*)&g_vadj[v_off  + (size_t)(c0+ci)*128 + d0] =
                make_float4(av[ci][0], av[ci][1], av[ci][2], av[ci][3]);
            *(float4*)&g_kcd [kcd_off + (size_t)(c0+ci)*128 + d0] =
                make_float4(ak[ci][0], ak[ci][1], ak[ci][2], ak[ci][3]);
        }
    }
}

// -------- sequential scan over chunks; 512 threads, dv-tile 64, grid (64,2) --------
__global__ void __launch_bounds__(512, 1) scan_kernel() {
    extern __shared__ float sm[];
    float* q_s    = sm;
    float* k_s    = q_s   + 64*SW;
    float* kcd_s  = k_s   + 64*SW;
    float* attn_s = kcd_s + 64*SW;
    float* vadj_s = attn_s + 4096;
    float* vnew_s = vadj_s + 4096;
    float* vek_s  = vnew_s + 4096;
    float* st     = vek_s  + 4096;
    __shared__ float gc_s[64], eg_s[64], ek_s[64];

    int bh = blockIdx.x, dvt = blockIdx.y;
    int b = bh >> 5, h = bh & 31, hq = h >> 1;
    int tid = threadIdx.x;
    int dv0 = (tid & 15) * 4;
    int grp = tid >> 4;

    for (int i = tid; i < 128 * 64; i += 512) st[i] = 0.f;

    for (int n = 0; n < NCH; n++) {
        size_t qk_off = (((size_t)b*HKq + hq)*S_ + (size_t)n*CHUNK) * DKd;
        size_t kv_off = (((size_t)b*HVv + h )*S_ + (size_t)n*CHUNK) * DKd;
        size_t gb_off = ((size_t)b*HVv + h)*S_ + (size_t)n*CHUNK;
        __syncthreads();
        for (int idx = tid; idx < 2048; idx += 512) {
            int r = idx >> 5, d = (idx & 31) * 4;
            *(float4*)&q_s  [r*SW + d] = *(const float4*)&g_q  [qk_off + (size_t)r*128 + d];
            *(float4*)&k_s  [r*SW + d] = *(const float4*)&g_k  [qk_off + (size_t)r*128 + d];
            *(float4*)&kcd_s[r*SW + d] = *(const float4*)&g_kcd[kv_off + (size_t)r*128 + d];
        }
        for (int idx = tid; idx < 1024; idx += 512)
            *(float4*)&attn_s[idx*4] = *(const float4*)&g_attn[gb_off*CHUNK + idx*4];
        for (int idx = tid; idx < 1024; idx += 512) {
            int c = idx >> 4, d = (idx & 15) * 4;
            *(float4*)&vadj_s[c*64 + d] =
                *(const float4*)&g_vadj[kv_off + (size_t)c*128 + dvt*64 + d];
        }
        if (tid < 64) { float gv = g_gc[gb_off + tid]; gc_s[tid] = gv; eg_s[tid] = expf(gv); }
        __syncthreads();
        if (tid < 64) ek_s[tid] = expf(gc_s[63] - gc_s[tid]);

        {
            int c0 = grp * 2;
            float a0[4], a1[4];
            *(float4*)a0 = *(float4*)&vadj_s[c0*64 + dv0];
            *(float4*)a1 = *(float4*)&vadj_s[(c0+1)*64 + dv0];
            for (int dk = 0; dk < 128; dk++) {
                float4 s4 = *(float4*)&st[dk*64 + dv0];
                float k0v = kcd_s[c0*SW + dk], k1v = kcd_s[(c0+1)*SW + dk];
                a0[0] -= k0v*s4.x; a0[1] -= k0v*s4.y; a0[2] -= k0v*s4.z; a0[3] -= k0v*s4.w;
                a1[0] -= k1v*s4.x; a1[1] -= k1v*s4.y; a1[2] -= k1v*s4.z; a1[3] -= k1v*s4.w;
            }
            *(float4*)&vnew_s[c0*64 + dv0]     = *(float4*)a0;
            *(float4*)&vnew_s[(c0+1)*64 + dv0] = *(float4*)a1;
            float e0 = ek_s[c0], e1 = ek_s[c0+1];
            *(float4*)&vek_s[c0*64 + dv0] =
                make_float4(a0[0]*e0, a0[1]*e0, a0[2]*e0, a0[3]*e0);
            *(float4*)&vek_s[(c0+1)*64 + dv0] =
                make_float4(a1[0]*e1, a1[1]*e1, a1[2]*e1, a1[3]*e1);
        }
        __syncthreads();

        {
            int c0 = grp * 2;
            float o0[4] = {}, o1[4] = {};
            for (int dk = 0; dk < 128; dk++) {
                float4 s4 = *(float4*)&st[dk*64 + dv0];
                float q0 = q_s[c0*SW + dk], q1 = q_s[(c0+1)*SW + dk];
                o0[0] += q0*s4.x; o0[1] += q0*s4.y; o0[2] += q0*s4.z; o0[3] += q0*s4.w;
                o1[0] += q1*s4.x; o1[1] += q1*s4.y; o1[2] += q1*s4.z; o1[3] += q1*s4.w;
            }
            float e0 = eg_s[c0], e1 = eg_s[c0+1];
#pragma unroll
            for (int x = 0; x < 4; x++) { o0[x] *= e0; o1[x] *= e1; }
            for (int j = 0; j < 64; j++) {
                float4 v4 = *(float4*)&vnew_s[j*64 + dv0];
                float a0v = attn_s[c0*64 + j], a1v = attn_s[(c0+1)*64 + j];
                o0[0] += a0v*v4.x; o0[1] += a0v*v4.y; o0[2] += a0v*v4.z; o0[3] += a0v*v4.w;
                o1[0] += a1v*v4.x; o1[1] += a1v*v4.y; o1[2] += a1v*v4.z; o1[3] += a1v*v4.w;
            }
            size_t ob = ((size_t)b*S_ + (size_t)n*CHUNK) * VALUE_DIM + (size_t)h*DVd + dvt*64 + dv0;
            *(float4*)&g_o[ob + (size_t)c0*VALUE_DIM]     = *(float4*)o0;
            *(float4*)&g_o[ob + (size_t)(c0+1)*VALUE_DIM] = *(float4*)o1;
        }

        {
            int dk0 = grp * 4;
            float egl = eg_s[63];
            float sa[4][4];
#pragma unroll
            for (int i = 0; i < 4; i++) {
                float4 s4 = *(float4*)&st[(dk0+i)*64 + dv0];
                sa[i][0] = s4.x*egl; sa[i][1] = s4.y*egl; sa[i][2] = s4.z*egl; sa[i][3] = s4.w*egl;
            }
            for (int c = 0; c < 64; c++) {
                float4 v4 = *(float4*)&vek_s[c*64 + dv0];
                float4 k4 = *(float4*)&k_s[c*SW + dk0];
                sa[0][0] += k4.x*v4.x; sa[0][1] += k4.x*v4.y; sa[0][2] += k4.x*v4.z; sa[0][3] += k4.x*v4.w;
                sa[1][0] += k4.y*v4.x; sa[1][1] += k4.y*v4.y; sa[1][2] += k4.y*v4.z; sa[1][3] += k4.y*v4.w;
                sa[2][0] += k4.z*v4.x; sa[2][1] += k4.z*v4.y; sa[2][2] += k4.z*v4.z; sa[2][3] += k4.z*v4.w;
                sa[3][0] += k4.w*v4.x; sa[3][1] += k4.w*v4.y; sa[3][2] += k4.w*v4.z; sa[3][3] += k4.w*v4.w;
            }
            __syncthreads();
#pragma unroll
            for (int i = 0; i < 4; i++)
                *(float4*)&st[(dk0+i)*64 + dv0] =
                    make_float4(sa[i][0], sa[i][1], sa[i][2], sa[i][3]);
        }
    }
}

// -------- gated RMSNorm -> fp16 directly into GEMM2 A buffer --------
__global__ void gated_norm(const float* __restrict__ nw) {
    int bs = blockIdx.x;
    int warp = threadIdx.x >> 5, lane = threadIdx.x & 31;
    for (int h = warp; h < HVv; h += 8) {
        size_t off = (size_t)bs * VALUE_DIM + (size_t)h * DVd;
        float4 v = ((float4*)(g_o + off))[lane];
        float ss = v.x*v.x + v.y*v.y + v.z*v.z + v.w*v.w;
#pragma unroll
        for (int o = 16; o; o >>= 1) ss += __shfl_xor_sync(~0u, ss, o);
        float r = rsqrtf(ss / 128.f + 1e-6f);
        size_t zoff = (size_t)bs * QKVZ_N + 2*KEY_DIM + VALUE_DIM + (size_t)h * DVd;
        float4 z = ((const float4*)(g_qkvz + zoff))[lane];
        float4 w = ((const float4*)nw)[lane];
        float r0 = v.x * r * w.x * (z.x / (1.f + expf(-z.x)));
        float r1 = v.y * r * w.y * (z.y / (1.f + expf(-z.y)));
        float r2 = v.z * r * w.z * (z.z / (1.f + expf(-z.z)));
        float r3 = v.w * r * w.w * (z.w / (1.f + expf(-z.w)));
        __half2 h0 = __floats2half2_rn(r0, r1);
        __half2 h1 = __floats2half2_rn(r2, r3);
        uint2 hv; hv.x = *(uint32_t*)&h0; hv.y = *(uint32_t*)&h1;
        ((uint2*)(g_r + off))[lane] = hv;
    }
}

// ---------------- launcher (single stream, R7 structure) ----------------
extern "C" void kernel_launch(void* const* d_in, const int* in_sizes, int n_in,
                              void* d_out, int out_size) {
    const float* hidden = (const float*)d_in[0];
    const float* Wqkvz  = (const float*)d_in[1];
    const float* Wba    = (const float*)d_in[2];
    const float* convw  = (const float*)d_in[3];
    const float* dtb    = (const float*)d_in[4];
    const float* Alog   = (const float*)d_in[5];
    const float* nw     = (const float*)d_in[6];
    const float* Wout   = (const float*)d_in[7];
    float* out = (float*)d_out;

    float *qkvz_p;
    __half *p_p, *r_p;
    cudaGetSymbolAddress((void**)&qkvz_p, g_qkvz);
    cudaGetSymbolAddress((void**)&p_p, g_p);
    cudaGetSymbolAddress((void**)&r_p, g_r);

    const int SMEM3 = (3*64*SW + 64*64 + 64*65) * 4;
    const int SMEM4 = (3*64*SW + 4*4096 + 128*64) * 4;
    const int SMEM_MM = NSTG * STG1 * 2;
    cudaFuncSetAttribute(chunk_prep, cudaFuncAttributeMaxDynamicSharedMemorySize, SMEM3);
    cudaFuncSetAttribute(scan_kernel, cudaFuncAttributeMaxDynamicSharedMemorySize, SMEM4);
    cudaFuncSetAttribute(mmgemm<0>, cudaFuncAttributeMaxDynamicSharedMemorySize, SMEM_MM);
    cudaFuncSetAttribute(mmgemm<1>, cudaFuncAttributeMaxDynamicSharedMemorySize, SMEM_MM);

    // --- GEMM1: qkvz = hidden @ W_qkvz (fp16-accum probe) ---
    cvt_h<<<(BSz*(size_t)HID)/1024, 256>>>(hidden, p_p);
    cvt_T<<<dim3(QKVZ_N/32, HID/32), dim3(32,8)>>>(Wqkvz, r_p, HID, QKVZ_N);
    mmgemm<1><<<dim3(BSz/128, QKVZ_N/128), 256, SMEM_MM>>>(p_p, r_p, qkvz_p, BSz, QKVZ_N, HID);

    // --- BA projection (split-K; reduce fused into conv_gate) ---
    gemm_ba_part<<<dim3(BSz/64, 8), 256>>>(hidden, Wba);

    // --- conv + gates, chunk prep, scan, norm ---
    conv_gate<<<BSz, 256>>>(convw, dtb, Alog);
    chunk_prep<<<B_*HVv*NCH, 256, SMEM3>>>();
    scan_kernel<<<dim3(B_*HVv, 2), 512, SMEM4>>>();
    gated_norm<<<BSz, 256>>>(nw);

    // --- GEMM2: out = o @ W_out (fp32-accum control) ---
    cvt_T<<<dim3(HID/32, VALUE_DIM/32), dim3(32,8)>>>(Wout, p_p, VALUE_DIM, HID);
    mmgemm<0><<<dim3(BSz/128, HID/128), 256, SMEM_MM>>>(r_p, p_p, out, BSz, HID, VALUE_DIM);
}

// round 11
// speedup vs baseline: 1.1547x; 1.1547x over previous
#include <cuda_runtime.h>
#include <cuda_bf16.h>
#include <cuda_fp16.h>
#include <math.h>
#include <stdint.h>

// ---------------- problem constants ----------------
#define B_   2
#define S_   2048
#define HID  2048
#define HKq  16
#define HVv  32
#define DKd  128
#define DVd  128
#define KC   4
#define CHUNK 64
#define NCH  (S_/CHUNK)          // 32
#define KEY_DIM 2048
#define VALUE_DIM 4096
#define CONV_DIM 8192
#define QKVZ_N 12288
#define BSz  (B_*S_)             // 4096
#define QSCALE 0.08838834764831845f   // DK^-0.5
#define SW 132                   // float4-aligned, conflict-free smem row stride

// ---------------- scratch (static device memory; no allocations) ------------
__device__ float g_qkvz[(size_t)BSz*QKVZ_N];               // [BS,12288] q|k|v|z
__device__ float g_bap[(size_t)8*BSz*64];                  // split-K partials
__device__ float g_q[(size_t)B_*HKq*S_*DKd];
__device__ float g_k[(size_t)B_*HKq*S_*DKd];
__device__ float g_v[(size_t)B_*HVv*S_*DVd];
__device__ float g_g[(size_t)B_*HVv*S_];
__device__ float g_beta[(size_t)B_*HVv*S_];
__device__ float g_gc[(size_t)B_*HVv*S_];
__device__ float g_vadj[(size_t)B_*HVv*S_*DVd];
__device__ float g_kcd[(size_t)B_*HVv*S_*DKd];
__device__ float g_attn[(size_t)B_*HVv*S_*CHUNK];
__device__ float g_o[(size_t)BSz*VALUE_DIM];

// fp16 operand buffers
__device__ __half g_p [(size_t)8388608];    // A1 (hidden) / B2t (Wout^T)
__device__ __half g_r [(size_t)25165824];   // B1t (Wqkvz^T) ; later A2 (gated_norm out)

__device__ __forceinline__ uint32_t smem_u32(const void* p) {
    uint32_t a;
    asm("{ .reg .u64 t; cvta.to.shared.u64 t, %1; cvt.u32.u64 %0, t; }" : "=r"(a) : "l"(p));
    return a;
}

// ---------------- fp32 -> fp16 (elementwise, float4) ----------------
__global__ void cvt_h(const float* __restrict__ X, __half* __restrict__ H) {
    size_t i = ((size_t)blockIdx.x * 256 + threadIdx.x) * 4;
    float4 v = *(const float4*)&X[i];
    __half2 h0 = __floats2half2_rn(v.x, v.y);
    __half2 h1 = __floats2half2_rn(v.z, v.w);
    uint2 hv;
    hv.x = *(uint32_t*)&h0; hv.y = *(uint32_t*)&h1;
    *(uint2*)&H[i] = hv;
}

// ---------------- fp32 [K,N] -> fp16 [N,K] transpose ----------------
__global__ void cvt_T(const float* __restrict__ W, __half* __restrict__ Ht, int K, int N) {
    __shared__ float tile[32][33];
    int n0 = blockIdx.x * 32, k0 = blockIdx.y * 32;
    int tx = threadIdx.x, ty = threadIdx.y;   // 32 x 8
#pragma unroll
    for (int j = 0; j < 32; j += 8)
        tile[ty + j][tx] = W[(size_t)(k0 + ty + j) * N + n0 + tx];
    __syncthreads();
#pragma unroll
    for (int j = 0; j < 32; j += 8)
        Ht[(size_t)(n0 + ty + j) * K + k0 + tx] = __float2half_rn(tile[tx][ty + j]);
}

// ============ fp16 HMMA GEMM: C[M,N] = A[M,K] @ Bt[N,K]^T (fp32 accum) ============
#define PSH 40
#define TEN2 (128*PSH)
#define STG1 (2*TEN2)
#define NSTG 4

__device__ __forceinline__ void mma_f16(float* c, const uint32_t* a, const uint32_t* b) {
    asm volatile("mma.sync.aligned.m16n8k16.row.col.f32.f16.f16.f32 "
                 "{%0,%1,%2,%3}, {%4,%5,%6,%7}, {%8,%9}, {%0,%1,%2,%3};"
                 : "+f"(c[0]), "+f"(c[1]), "+f"(c[2]), "+f"(c[3])
                 : "r"(a[0]), "r"(a[1]), "r"(a[2]), "r"(a[3]), "r"(b[0]), "r"(b[1]));
}
__device__ __forceinline__ void ldmx4(uint32_t* r, uint32_t addr) {
    asm volatile("ldmatrix.sync.aligned.m8n8.x4.shared.b16 {%0,%1,%2,%3}, [%4];"
                 : "=r"(r[0]), "=r"(r[1]), "=r"(r[2]), "=r"(r[3]) : "r"(addr));
}

__device__ __forceinline__ void stage_load(uint32_t sbase_b, int stage,
    const __half* a0, const __half* b0, int K, int kt, int tid)
{
    const __half* gp[2] = {a0, b0};
    uint32_t st_b = sbase_b + (uint32_t)stage * (STG1 * 2);
#pragma unroll
    for (int t = 0; t < 2; t++) {
        uint32_t tb = st_b + (uint32_t)t * (TEN2 * 2);
#pragma unroll
        for (int j = 0; j < 2; j++) {
            int idx = j * 256 + tid;
            int row = idx >> 2, c16 = idx & 3;
            uint32_t sa = tb + (uint32_t)(row * (PSH*2) + c16 * 16);
            const void* ga = gp[t] + (size_t)row * K + (size_t)kt * 32 + c16 * 8;
            asm volatile("cp.async.cg.shared.global [%0], [%1], 16;" :: "r"(sa), "l"(ga));
        }
    }
    asm volatile("cp.async.commit_group;" ::: "memory");
}

__global__ void __launch_bounds__(256, 2) mmgemm(
    const __half* __restrict__ Ah, const __half* __restrict__ Bh,
    float* __restrict__ C, int M, int N, int K)
{
    extern __shared__ __half smem[];
    uint32_t sbase = smem_u32(smem);
    int tid = threadIdx.x, lane = tid & 31, wid = tid >> 5;
    int warpM = wid >> 2, warpN = wid & 3;
    int bm = blockIdx.x, bn = blockIdx.y;
    const int T = K >> 5;

    const __half* a0 = Ah + (size_t)bm * 128 * K;
    const __half* b0 = Bh + (size_t)bn * 128 * K;

    int g = lane >> 3, lr = lane & 7;
    uint32_t aoff = (uint32_t)((warpM*64 + (g&1)*8 + lr) * PSH + (g>>1)*8);
    uint32_t boff = (uint32_t)((warpN*32 + (g>>1)*8 + lr) * PSH + (g&1)*8);

    float acc[4][4][4];
#pragma unroll
    for (int i = 0; i < 4; i++)
#pragma unroll
        for (int j = 0; j < 4; j++)
#pragma unroll
            for (int r = 0; r < 4; r++) acc[i][j][r] = 0.f;

    stage_load(sbase, 0, a0, b0, K, 0, tid);
    stage_load(sbase, 1, a0, b0, K, 1, tid);
    stage_load(sbase, 2, a0, b0, K, 2, tid);

    for (int kt = 0; kt < T; kt++) {
        int rem = T - 1 - kt;
        if (rem >= 2)      asm volatile("cp.async.wait_group 2;" ::: "memory");
        else if (rem == 1) asm volatile("cp.async.wait_group 1;" ::: "memory");
        else               asm volatile("cp.async.wait_group 0;" ::: "memory");
        __syncthreads();
        if (kt + 3 < T) stage_load(sbase, (kt + 3) % NSTG, a0, b0, K, kt + 3, tid);

        uint32_t st = sbase + (uint32_t)(kt % NSTG) * (STG1 * 2);
        uint32_t sA = st, sB = st + TEN2*2;
#pragma unroll
        for (int ks = 0; ks < 2; ks++) {
            int kk = ks * 16;
            uint32_t ah[4][4], bh[4][2];
#pragma unroll
            for (int mi = 0; mi < 4; mi++)
                ldmx4(ah[mi], sA + (aoff + mi*16*PSH + kk) * 2);
#pragma unroll
            for (int p = 0; p < 2; p++) {
                uint32_t rh[4];
                ldmx4(rh, sB + (boff + p*16*PSH + kk) * 2);
                bh[2*p][0] = rh[0]; bh[2*p][1] = rh[1];
                bh[2*p+1][0] = rh[2]; bh[2*p+1][1] = rh[3];
            }
#pragma unroll
            for (int mi = 0; mi < 4; mi++)
#pragma unroll
                for (int ni = 0; ni < 4; ni++)
                    mma_f16(acc[mi][ni], ah[mi], bh[ni]);
        }
        __syncthreads();
    }

    int rr = lane >> 2, cc = (lane & 3) * 2;
#pragma unroll
    for (int mi = 0; mi < 4; mi++) {
        int row0 = bm * 128 + warpM * 64 + mi * 16 + rr;
#pragma unroll
        for (int ni = 0; ni < 4; ni++) {
            int col = bn * 128 + warpN * 32 + ni * 8 + cc;
            float2 v0 = make_float2(acc[mi][ni][0], acc[mi][ni][1]);
            float2 v1 = make_float2(acc[mi][ni][2], acc[mi][ni][3]);
            *(float2*)&C[(size_t)row0 * N + col]       = v0;
            *(float2*)&C[(size_t)(row0 + 8) * N + col] = v1;
        }
    }
}

// ------------- BA projection split-K -> partials -------------
__global__ void gemm_ba_part(const float* __restrict__ X, const float* __restrict__ W) {
    __shared__ float Xs[64][65];
    __shared__ float Ws[64][64];
    int tid = threadIdx.x;
    int row0 = blockIdx.x * 64;
    int kbase = blockIdx.y * 256;
    int col = (tid & 15) * 4;
    int r0 = (tid >> 4) * 4;
    float acc[4][4] = {};
    for (int k0 = kbase; k0 < kbase + 256; k0 += 64) {
#pragma unroll
        for (int j = 0; j < 16; j++) {
            int idx = j * 256 + tid;
            int r = idx >> 6, kk = idx & 63;
            Xs[r][kk] = X[(size_t)(row0 + r) * HID + k0 + kk];
        }
#pragma unroll
        for (int j = 0; j < 16; j++) {
            int idx = j * 256 + tid;
            int kk = idx >> 6, c = idx & 63;
            Ws[kk][c] = W[(size_t)(k0 + kk) * 64 + c];
        }
        __syncthreads();
#pragma unroll 8
        for (int kk = 0; kk < 64; kk++) {
            float4 b = *(float4*)&Ws[kk][col];
#pragma unroll
            for (int r = 0; r < 4; r++) {
                float a = Xs[r0 + r][kk];
                acc[r][0] += a*b.x; acc[r][1] += a*b.y; acc[r][2] += a*b.z; acc[r][3] += a*b.w;
            }
        }
        __syncthreads();
    }
    float* dst = g_bap + (size_t)blockIdx.y * BSz * 64;
#pragma unroll
    for (int r = 0; r < 4; r++)
        *(float4*)&dst[(size_t)(row0 + r0 + r) * 64 + col] =
            make_float4(acc[r][0], acc[r][1], acc[r][2], acc[r][3]);
}

// -------- conv + silu + l2norm + head transpose + gates (float4-vectorized) --------
__global__ void conv_gate(const float* __restrict__ cw, const float* __restrict__ dtb,
                          const float* __restrict__ Alog) {
    int bs = blockIdx.x;
    int b = bs / S_, s = bs % S_;
    int tid = threadIdx.x;
    __shared__ float cs[CONV_DIM];
    __shared__ float hsum[32];
    const float* base = g_qkvz + (size_t)bs * QKVZ_N;
    const float4* cw4 = (const float4*)cw;   // cw[c][0..3] = one float4 per channel

    // conv over channel quads: per quad = 4 tap-float4 + up to 4 row-float4 loads
    for (int c4 = tid; c4 < CONV_DIM / 4; c4 += 256) {
        int c = c4 * 4;
        float4 w0 = cw4[c + 0], w1 = cw4[c + 1], w2 = cw4[c + 2], w3 = cw4[c + 3];
        float4 x3 = *(const float4*)&base[c];                                   // row s (tap 3)
        float4 r;
        r.x = x3.x * w0.w; r.y = x3.y * w1.w; r.z = x3.z * w2.w; r.w = x3.w * w3.w;
        if (s >= 1) {
            float4 x2 = *(const float4*)&base[c - (size_t)QKVZ_N];
            r.x += x2.x * w0.z; r.y += x2.y * w1.z; r.z += x2.z * w2.z; r.w += x2.w * w3.z;
        }
        if (s >= 2) {
            float4 x1 = *(const float4*)&base[c - (size_t)2*QKVZ_N];
            r.x += x1.x * w0.y; r.y += x1.y * w1.y; r.z += x1.z * w2.y; r.w += x1.w * w3.y;
        }
        if (s >= 3) {
            float4 x0 = *(const float4*)&base[c - (size_t)3*QKVZ_N];
            r.x += x0.x * w0.x; r.y += x0.y * w1.x; r.z += x0.z * w2.x; r.w += x0.w * w3.x;
        }
        r.x = r.x / (1.f + __expf(-r.x));
        r.y = r.y / (1.f + __expf(-r.y));
        r.z = r.z / (1.f + __expf(-r.z));
        r.w = r.w / (1.f + __expf(-r.w));
        *(float4*)&cs[c] = r;
    }
    __syncthreads();
    int warp = tid >> 5, lane = tid & 31;
    for (int h = warp; h < 32; h += 8) {
        float ss = 0.f;
        for (int d = lane; d < 128; d += 32) { float v = cs[h*128 + d]; ss += v * v; }
#pragma unroll
        for (int o = 16; o; o >>= 1) ss += __shfl_xor_sync(~0u, ss, o);
        if (!lane) hsum[h] = rsqrtf(ss + 1e-6f);
    }
    __syncthreads();
    // vectorized normalize + scatter stores
    for (int c4 = tid; c4 < KEY_DIM / 4; c4 += 256) {
        int c = c4 * 4;
        int h = c >> 7, d = c & 127;
        float sc = hsum[h] * QSCALE;
        float4 v = *(float4*)&cs[c];
        v.x *= sc; v.y *= sc; v.z *= sc; v.w *= sc;
        *(float4*)&g_q[(((size_t)b*HKq + h)*S_ + s)*DKd + d] = v;
    }
    for (int c4 = tid; c4 < KEY_DIM / 4; c4 += 256) {
        int c = c4 * 4;
        int h = c >> 7, d = c & 127;
        float sc = hsum[16 + h];
        float4 v = *(float4*)&cs[KEY_DIM + c];
        v.x *= sc; v.y *= sc; v.z *= sc; v.w *= sc;
        *(float4*)&g_k[(((size_t)b*HKq + h)*S_ + s)*DKd + d] = v;
    }
    for (int c4 = tid; c4 < VALUE_DIM / 4; c4 += 256) {
        int c = c4 * 4;
        int h = c >> 7, d = c & 127;
        float4 v = *(float4*)&cs[2*KEY_DIM + c];
        *(float4*)&g_v[(((size_t)b*HVv + h)*S_ + s)*DVd + d] = v;
    }
    if (tid < 64) {
        float bb = 0.f;
#pragma unroll
        for (int p = 0; p < 8; p++) bb += g_bap[(size_t)p * BSz * 64 + (size_t)bs * 64 + tid];
        if (tid < 32) {
            g_beta[((size_t)b*HVv + tid)*S_ + s] = 1.f / (1.f + expf(-bb));
        } else {
            int h = tid - 32;
            float a = bb + dtb[h];
            float sp = (a > 20.f) ? a : log1pf(expf(a));
            g_g[((size_t)b*HVv + h)*S_ + s] = -expf(Alog[h]) * sp;
        }
    }
}

// -------- per-(b,h,chunk) intra-chunk quantities (register-tiled float4) --------
__global__ void __launch_bounds__(256, 1) chunk_prep() {
    extern __shared__ float sm[];
    float* q_s  = sm;
    float* k_s  = q_s  + 64*SW;
    float* vb_s = k_s  + 64*SW;
    float* A_s  = vb_s + 64*SW;
    float* T_s  = A_s  + 64*64;
    __shared__ float gc_s[64], beta_s[64], kbe_s[64];

    int blk = blockIdx.x;
    int n = blk & 31, h = (blk >> 5) & 31, b = blk >> 10;
    int hq = h >> 1;
    int tid = threadIdx.x;

    size_t qk_off = (((size_t)b*HKq + hq)*S_ + (size_t)n*CHUNK) * DKd;
    size_t v_off  = (((size_t)b*HVv + h )*S_ + (size_t)n*CHUNK) * DVd;
    size_t gb_off = ((size_t)b*HVv + h)*S_ + (size_t)n*CHUNK;

    if (tid < 64) { gc_s[tid] = g_g[gb_off + tid]; beta_s[tid] = g_beta[gb_off + tid]; }
    __syncthreads();
    if (tid == 0) { for (int i = 1; i < 64; i++) gc_s[i] += gc_s[i - 1]; }
    __syncthreads();
    if (tid < 64) {
        g_gc[gb_off + tid] = gc_s[tid];
        kbe_s[tid] = beta_s[tid] * expf(gc_s[tid]);
    }
    for (int idx = tid; idx < 2048; idx += 256) {
        int r = idx >> 5, d = (idx & 31) * 4;
        float4 qv = *(const float4*)&g_q[qk_off + (size_t)r*128 + d];
        float4 kv = *(const float4*)&g_k[qk_off + (size_t)r*128 + d];
        float4 vv = *(const float4*)&g_v[v_off  + (size_t)r*128 + d];
        float be = beta_s[r];
        vv.x *= be; vv.y *= be; vv.z *= be; vv.w *= be;
        *(float4*)&q_s [r*SW + d] = qv;
        *(float4*)&k_s [r*SW + d] = kv;
        *(float4*)&vb_s[r*SW + d] = vv;
    }
    __syncthreads();

    {
        int jt = tid & 15, ct = tid >> 4;
        int j0 = jt * 4, c0 = ct * 4;
        float aa[4][4] = {}, aq[4][4] = {};
        for (int dk = 0; dk < 128; dk += 4) {
            float4 kj[4], kc[4], qc[4];
#pragma unroll
            for (int x = 0; x < 4; x++) kj[x] = *(float4*)&k_s[(j0+x)*SW + dk];
#pragma unroll
            for (int x = 0; x < 4; x++) kc[x] = *(float4*)&k_s[(c0+x)*SW + dk];
#pragma unroll
            for (int x = 0; x < 4; x++) qc[x] = *(float4*)&q_s[(c0+x)*SW + dk];
#pragma unroll
            for (int ci = 0; ci < 4; ci++)
#pragma unroll
                for (int ji = 0; ji < 4; ji++) {
                    aa[ci][ji] += kc[ci].x*kj[ji].x + kc[ci].y*kj[ji].y
                                + kc[ci].z*kj[ji].z + kc[ci].w*kj[ji].w;
                    aq[ci][ji] += qc[ci].x*kj[ji].x + qc[ci].y*kj[ji].y
                                + qc[ci].z*kj[ji].z + qc[ci].w*kj[ji].w;
                }
        }
        size_t at_off = gb_off * CHUNK;
#pragma unroll
        for (int ci = 0; ci < 4; ci++)
#pragma unroll
            for (int ji = 0; ji < 4; ji++) {
                int c = c0 + ci, j = j0 + ji;
                float e = __expf(gc_s[c] - gc_s[j]);
                A_s[c*64 + j] = (j < c) ? aa[ci][ji] * beta_s[c] * e : 0.f;
                g_attn[at_off + c*64 + j] = (j <= c) ? aq[ci][ji] * e : 0.f;
            }
    }
    __syncthreads();

    if (tid < 64) {
        int col = tid;
        for (int c = 0; c < 64; c++) {
            float ssum = (c == col) ? 1.f : 0.f;
            for (int j = col; j < c; j++) ssum -= A_s[c*64 + j] * T_s[j*65 + col];
            T_s[c*65 + col] = (c >= col) ? ssum : 0.f;
        }
    }
    __syncthreads();

    {
        int ct8 = tid >> 5, lane = tid & 31;
        int c0 = ct8 * 8, d0 = lane * 4;
        float av[8][4] = {}, ak[8][4] = {};
        int jmax = c0 + 8;
        for (int j = 0; j < jmax; j++) {
            float4 vv = *(float4*)&vb_s[j*SW + d0];
            float4 kk = *(float4*)&k_s [j*SW + d0];
            float kb = kbe_s[j];
            kk.x *= kb; kk.y *= kb; kk.z *= kb; kk.w *= kb;
#pragma unroll
            for (int ci = 0; ci < 8; ci++) {
                float t = T_s[(c0+ci)*65 + j];
                av[ci][0] += t*vv.x; av[ci][1] += t*vv.y; av[ci][2] += t*vv.z; av[ci][3] += t*vv.w;
                ak[ci][0] += t*kk.x; ak[ci][1] += t*kk.y; ak[ci][2] += t*kk.z; ak[ci][3] += t*kk.w;
            }
        }
        size_t kcd_off = (((size_t)b*HVv + h)*S_ + (size_t)n*CHUNK) * DKd;
#pragma unroll
        for (int ci = 0; ci < 8; ci++) {
            *(float4*)&g_vadj[v_off  + (size_t)(c0+ci)*128 + d0] =
                make_float4(av[ci][0], av[ci][1], av[ci][2], av[ci][3]);
            *(float4*)&g_kcd [kcd_off + (size_t)(c0+ci)*128 + d0] =
                make_float4(ak[ci][0], ak[ci][1], ak[ci][2], ak[ci][3]);
        }
    }
}

// -------- sequential scan over chunks; 512 threads, dv-tile 64, grid (64,2) --------
__global__ void __launch_bounds__(512, 1) scan_kernel() {
    extern __shared__ float sm[];
    float* q_s    = sm;
    float* k_s    = q_s   + 64*SW;
    float* kcd_s  = k_s   + 64*SW;
    float* attn_s = kcd_s + 64*SW;
    float* vadj_s = attn_s + 4096;
    float* vnew_s = vadj_s + 4096;
    float* vek_s  = vnew_s + 4096;
    float* st     = vek_s  + 4096;
    __shared__ float gc_s[64], eg_s[64], ek_s[64];

    int bh = blockIdx.x, dvt = blockIdx.y;
    int b = bh >> 5, h = bh & 31, hq = h >> 1;
    int tid = threadIdx.x;
    int dv0 = (tid & 15) * 4;
    int grp = tid >> 4;

    for (int i = tid; i < 128 * 64; i += 512) st[i] = 0.f;

    for (int n = 0; n < NCH; n++) {
        size_t qk_off = (((size_t)b*HKq + hq)*S_ + (size_t)n*CHUNK) * DKd;
        size_t kv_off = (((size_t)b*HVv + h )*S_ + (size_t)n*CHUNK) * DKd;
        size_t gb_off = ((size_t)b*HVv + h)*S_ + (size_t)n*CHUNK;
        __syncthreads();
        for (int idx = tid; idx < 2048; idx += 512) {
            int r = idx >> 5, d = (idx & 31) * 4;
            *(float4*)&q_s  [r*SW + d] = *(const float4*)&g_q  [qk_off + (size_t)r*128 + d];
            *(float4*)&k_s  [r*SW + d] = *(const float4*)&g_k  [qk_off + (size_t)r*128 + d];
            *(float4*)&kcd_s[r*SW + d] = *(const float4*)&g_kcd[kv_off + (size_t)r*128 + d];
        }
        for (int idx = tid; idx < 1024; idx += 512)
            *(float4*)&attn_s[idx*4] = *(const float4*)&g_attn[gb_off*CHUNK + idx*4];
        for (int idx = tid; idx < 1024; idx += 512) {
            int c = idx >> 4, d = (idx & 15) * 4;
            *(float4*)&vadj_s[c*64 + d] =
                *(const float4*)&g_vadj[kv_off + (size_t)c*128 + dvt*64 + d];
        }
        if (tid < 64) { float gv = g_gc[gb_off + tid]; gc_s[tid] = gv; eg_s[tid] = expf(gv); }
        __syncthreads();
        if (tid < 64) ek_s[tid] = expf(gc_s[63] - gc_s[tid]);

        {
            int c0 = grp * 2;
            float a0[4], a1[4];
            *(float4*)a0 = *(float4*)&vadj_s[c0*64 + dv0];
            *(float4*)a1 = *(float4*)&vadj_s[(c0+1)*64 + dv0];
            for (int dk = 0; dk < 128; dk++) {
                float4 s4 = *(float4*)&st[dk*64 + dv0];
                float k0v = kcd_s[c0*SW + dk], k1v = kcd_s[(c0+1)*SW + dk];
                a0[0] -= k0v*s4.x; a0[1] -= k0v*s4.y; a0[2] -= k0v*s4.z; a0[3] -= k0v*s4.w;
                a1[0] -= k1v*s4.x; a1[1] -= k1v*s4.y; a1[2] -= k1v*s4.z; a1[3] -= k1v*s4.w;
            }
            *(float4*)&vnew_s[c0*64 + dv0]     = *(float4*)a0;
            *(float4*)&vnew_s[(c0+1)*64 + dv0] = *(float4*)a1;
            float e0 = ek_s[c0], e1 = ek_s[c0+1];
            *(float4*)&vek_s[c0*64 + dv0] =
                make_float4(a0[0]*e0, a0[1]*e0, a0[2]*e0, a0[3]*e0);
            *(float4*)&vek_s[(c0+1)*64 + dv0] =
                make_float4(a1[0]*e1, a1[1]*e1, a1[2]*e1, a1[3]*e1);
        }
        __syncthreads();

        {
            int c0 = grp * 2;
            float o0[4] = {}, o1[4] = {};
            for (int dk = 0; dk < 128; dk++) {
                float4 s4 = *(float4*)&st[dk*64 + dv0];
                float q0 = q_s[c0*SW + dk], q1 = q_s[(c0+1)*SW + dk];
                o0[0] += q0*s4.x; o0[1] += q0*s4.y; o0[2] += q0*s4.z; o0[3] += q0*s4.w;
                o1[0] += q1*s4.x; o1[1] += q1*s4.y; o1[2] += q1*s4.z; o1[3] += q1*s4.w;
            }
            float e0 = eg_s[c0], e1 = eg_s[c0+1];
#pragma unroll
            for (int x = 0; x < 4; x++) { o0[x] *= e0; o1[x] *= e1; }
            for (int j = 0; j < 64; j++) {
                float4 v4 = *(float4*)&vnew_s[j*64 + dv0];
                float a0v = attn_s[c0*64 + j], a1v = attn_s[(c0+1)*64 + j];
                o0[0] += a0v*v4.x; o0[1] += a0v*v4.y; o0[2] += a0v*v4.z; o0[3] += a0v*v4.w;
                o1[0] += a1v*v4.x; o1[1] += a1v*v4.y; o1[2] += a1v*v4.z; o1[3] += a1v*v4.w;
            }
            size_t ob = ((size_t)b*S_ + (size_t)n*CHUNK) * VALUE_DIM + (size_t)h*DVd + dvt*64 + dv0;
            *(float4*)&g_o[ob + (size_t)c0*VALUE_DIM]     = *(float4*)o0;
            *(float4*)&g_o[ob + (size_t)(c0+1)*VALUE_DIM] = *(float4*)o1;
        }

        {
            int dk0 = grp * 4;
            float egl = eg_s[63];
            float sa[4][4];
#pragma unroll
            for (int i = 0; i < 4; i++) {
                float4 s4 = *(float4*)&st[(dk0+i)*64 + dv0];
                sa[i][0] = s4.x*egl; sa[i][1] = s4.y*egl; sa[i][2] = s4.z*egl; sa[i][3] = s4.w*egl;
            }
            for (int c = 0; c < 64; c++) {
                float4 v4 = *(float4*)&vek_s[c*64 + dv0];
                float4 k4 = *(float4*)&k_s[c*SW + dk0];
                sa[0][0] += k4.x*v4.x; sa[0][1] += k4.x*v4.y; sa[0][2] += k4.x*v4.z; sa[0][3] += k4.x*v4.w;
                sa[1][0] += k4.y*v4.x; sa[1][1] += k4.y*v4.y; sa[1][2] += k4.y*v4.z; sa[1][3] += k4.y*v4.w;
                sa[2][0] += k4.z*v4.x; sa[2][1] += k4.z*v4.y; sa[2][2] += k4.z*v4.z; sa[2][3] += k4.z*v4.w;
                sa[3][0] += k4.w*v4.x; sa[3][1] += k4.w*v4.y; sa[3][2] += k4.w*v4.z; sa[3][3] += k4.w*v4.w;
            }
            __syncthreads();
#pragma unroll
            for (int i = 0; i < 4; i++)
                *(float4*)&st[(dk0+i)*64 + dv0] =
                    make_float4(sa[i][0], sa[i][1], sa[i][2], sa[i][3]);
        }
    }
}

// -------- gated RMSNorm -> fp16 directly into GEMM2 A buffer --------
__global__ void gated_norm(const float* __restrict__ nw) {
    int bs = blockIdx.x;
    int warp = threadIdx.x >> 5, lane = threadIdx.x & 31;
    for (int h = warp; h < HVv; h += 8) {
        size_t off = (size_t)bs * VALUE_DIM + (size_t)h * DVd;
        float4 v = ((float4*)(g_o + off))[lane];
        float ss = v.x*v.x + v.y*v.y + v.z*v.z + v.w*v.w;
#pragma unroll
        for (int o = 16; o; o >>= 1) ss += __shfl_xor_sync(~0u, ss, o);
        float r = rsqrtf(ss / 128.f + 1e-6f);
        size_t zoff = (size_t)bs * QKVZ_N + 2*KEY_DIM + VALUE_DIM + (size_t)h * DVd;
        float4 z = ((const float4*)(g_qkvz + zoff))[lane];
        float4 w = ((const float4*)nw)[lane];
        float r0 = v.x * r * w.x * (z.x / (1.f + expf(-z.x)));
        float r1 = v.y * r * w.y * (z.y / (1.f + expf(-z.y)));
        float r2 = v.z * r * w.z * (z.z / (1.f + expf(-z.z)));
        float r3 = v.w * r * w.w * (z.w / (1.f + expf(-z.w)));
        __half2 h0 = __floats2half2_rn(r0, r1);
        __half2 h1 = __floats2half2_rn(r2, r3);
        uint2 hv; hv.x = *(uint32_t*)&h0; hv.y = *(uint32_t*)&h1;
        ((uint2*)(g_r + off))[lane] = hv;
    }
}

// ---------------- launcher (single stream, R7 structure) ----------------
extern "C" void kernel_launch(void* const* d_in, const int* in_sizes, int n_in,
                              void* d_out, int out_size) {
    const float* hidden = (const float*)d_in[0];
    const float* Wqkvz  = (const float*)d_in[1];
    const float* Wba    = (const float*)d_in[2];
    const float* convw  = (const float*)d_in[3];
    const float* dtb    = (const float*)d_in[4];
    const float* Alog   = (const float*)d_in[5];
    const float* nw     = (const float*)d_in[6];
    const float* Wout   = (const float*)d_in[7];
    float* out = (float*)d_out;

    float *qkvz_p;
    __half *p_p, *r_p;
    cudaGetSymbolAddress((void**)&qkvz_p, g_qkvz);
    cudaGetSymbolAddress((void**)&p_p, g_p);
    cudaGetSymbolAddress((void**)&r_p, g_r);

    const int SMEM3 = (3*64*SW + 64*64 + 64*65) * 4;
    const int SMEM4 = (3*64*SW + 4*4096 + 128*64) * 4;
    const int SMEM_MM = NSTG * STG1 * 2;
    cudaFuncSetAttribute(chunk_prep, cudaFuncAttributeMaxDynamicSharedMemorySize, SMEM3);
    cudaFuncSetAttribute(scan_kernel, cudaFuncAttributeMaxDynamicSharedMemorySize, SMEM4);
    cudaFuncSetAttribute(mmgemm, cudaFuncAttributeMaxDynamicSharedMemorySize, SMEM_MM);

    // --- GEMM1: qkvz = hidden @ W_qkvz ---
    cvt_h<<<(BSz*(size_t)HID)/1024, 256>>>(hidden, p_p);
    cvt_T<<<dim3(QKVZ_N/32, HID/32), dim3(32,8)>>>(Wqkvz, r_p, HID, QKVZ_N);
    mmgemm<<<dim3(BSz/128, QKVZ_N/128), 256, SMEM_MM>>>(p_p, r_p, qkvz_p, BSz, QKVZ_N, HID);

    // --- BA projection (split-K; reduce fused into conv_gate) ---
    gemm_ba_part<<<dim3(BSz/64, 8), 256>>>(hidden, Wba);

    // --- conv + gates, chunk prep, scan, norm ---
    conv_gate<<<BSz, 256>>>(convw, dtb, Alog);
    chunk_prep<<<B_*HVv*NCH, 256, SMEM3>>>();
    scan_kernel<<<dim3(B_*HVv, 2), 512, SMEM4>>>();
    gated_norm<<<BSz, 256>>>(nw);

    // --- GEMM2: out = o @ W_out (A written fp16 by gated_norm) ---
    cvt_T<<<dim3(HID/32, VALUE_DIM/32), dim3(32,8)>>>(Wout, p_p, VALUE_DIM, HID);
    mmgemm<<<dim3(BSz/128, HID/128), 256, SMEM_MM>>>(r_p, p_p, out, BSz, HID, VALUE_DIM);
}

// round 12
// speedup vs baseline: 1.3891x; 1.2030x over previous
#include <cuda_runtime.h>
#include <cuda_bf16.h>
#include <cuda_fp16.h>
#include <math.h>
#include <stdint.h>

// ---------------- problem constants ----------------
#define B_   2
#define S_   2048
#define HID  2048
#define HKq  16
#define HVv  32
#define DKd  128
#define DVd  128
#define KC   4
#define CHUNK 64
#define NCH  (S_/CHUNK)          // 32
#define KEY_DIM 2048
#define VALUE_DIM 4096
#define CONV_DIM 8192
#define QKVZ_N 12288
#define BSz  (B_*S_)             // 4096
#define QSCALE 0.08838834764831845f   // DK^-0.5
#define SW 132                   // float4-aligned, conflict-free smem row stride

// ---------------- scratch (static device memory; no allocations) ------------
__device__ float g_qkvz[(size_t)BSz*QKVZ_N];               // [BS,12288] q|k|v|z
__device__ float g_bap[(size_t)8*BSz*64];                  // split-K partials
__device__ float g_q[(size_t)B_*HKq*S_*DKd];
__device__ float g_k[(size_t)B_*HKq*S_*DKd];
__device__ float g_v[(size_t)B_*HVv*S_*DVd];
__device__ float g_g[(size_t)B_*HVv*S_];
__device__ float g_beta[(size_t)B_*HVv*S_];
__device__ float g_gc[(size_t)B_*HVv*S_];
__device__ float g_vadj[(size_t)B_*HVv*S_*DVd];
__device__ float g_kcd[(size_t)B_*HVv*S_*DKd];
__device__ float g_attn[(size_t)B_*HVv*S_*CHUNK];
__device__ float g_o[(size_t)BSz*VALUE_DIM];

// fp16 operand buffers
__device__ __half g_p [(size_t)8388608];    // A1 (hidden) / B2t (Wout^T)
__device__ __half g_r [(size_t)25165824];   // B1t (Wqkvz^T) ; later A2 (gated_norm out)

__device__ __forceinline__ uint32_t smem_u32(const void* p) {
    uint32_t a;
    asm("{ .reg .u64 t; cvta.to.shared.u64 t, %1; cvt.u32.u64 %0, t; }" : "=r"(a) : "l"(p));
    return a;
}

// ---------------- fp32 -> fp16 (elementwise, float4) ----------------
__global__ void cvt_h(const float* __restrict__ X, __half* __restrict__ H) {
    size_t i = ((size_t)blockIdx.x * 256 + threadIdx.x) * 4;
    float4 v = *(const float4*)&X[i];
    __half2 h0 = __floats2half2_rn(v.x, v.y);
    __half2 h1 = __floats2half2_rn(v.z, v.w);
    uint2 hv;
    hv.x = *(uint32_t*)&h0; hv.y = *(uint32_t*)&h1;
    *(uint2*)&H[i] = hv;
}

// ---------------- fp32 [K,N] -> fp16 [N,K] transpose ----------------
__global__ void cvt_T(const float* __restrict__ W, __half* __restrict__ Ht, int K, int N) {
    __shared__ float tile[32][33];
    int n0 = blockIdx.x * 32, k0 = blockIdx.y * 32;
    int tx = threadIdx.x, ty = threadIdx.y;   // 32 x 8
#pragma unroll
    for (int j = 0; j < 32; j += 8)
        tile[ty + j][tx] = W[(size_t)(k0 + ty + j) * N + n0 + tx];
    __syncthreads();
#pragma unroll
    for (int j = 0; j < 32; j += 8)
        Ht[(size_t)(n0 + ty + j) * K + k0 + tx] = __float2half_rn(tile[tx][ty + j]);
}

// ============ fp16 HMMA GEMM: C[M,N] = A[M,K] @ Bt[N,K]^T (fp32 accum) ============
#define PSH 40
#define TEN2 (128*PSH)
#define STG1 (2*TEN2)
#define NSTG 4

__device__ __forceinline__ void mma_f16(float* c, const uint32_t* a, const uint32_t* b) {
    asm volatile("mma.sync.aligned.m16n8k16.row.col.f32.f16.f16.f32 "
                 "{%0,%1,%2,%3}, {%4,%5,%6,%7}, {%8,%9}, {%0,%1,%2,%3};"
                 : "+f"(c[0]), "+f"(c[1]), "+f"(c[2]), "+f"(c[3])
                 : "r"(a[0]), "r"(a[1]), "r"(a[2]), "r"(a[3]), "r"(b[0]), "r"(b[1]));
}
__device__ __forceinline__ void ldmx4(uint32_t* r, uint32_t addr) {
    asm volatile("ldmatrix.sync.aligned.m8n8.x4.shared.b16 {%0,%1,%2,%3}, [%4];"
                 : "=r"(r[0]), "=r"(r[1]), "=r"(r[2]), "=r"(r[3]) : "r"(addr));
}

__device__ __forceinline__ void stage_load(uint32_t sbase_b, int stage,
    const __half* a0, const __half* b0, int K, int kt, int tid)
{
    const __half* gp[2] = {a0, b0};
    uint32_t st_b = sbase_b + (uint32_t)stage * (STG1 * 2);
#pragma unroll
    for (int t = 0; t < 2; t++) {
        uint32_t tb = st_b + (uint32_t)t * (TEN2 * 2);
#pragma unroll
        for (int j = 0; j < 2; j++) {
            int idx = j * 256 + tid;
            int row = idx >> 2, c16 = idx & 3;
            uint32_t sa = tb + (uint32_t)(row * (PSH*2) + c16 * 16);
            const void* ga = gp[t] + (size_t)row * K + (size_t)kt * 32 + c16 * 8;
            asm volatile("cp.async.cg.shared.global [%0], [%1], 16;" :: "r"(sa), "l"(ga));
        }
    }
    asm volatile("cp.async.commit_group;" ::: "memory");
}

__global__ void __launch_bounds__(256, 2) mmgemm(
    const __half* __restrict__ Ah, const __half* __restrict__ Bh,
    float* __restrict__ C, int M, int N, int K)
{
    extern __shared__ __half smem[];
    uint32_t sbase = smem_u32(smem);
    int tid = threadIdx.x, lane = tid & 31, wid = tid >> 5;
    int warpM = wid >> 2, warpN = wid & 3;
    int bm = blockIdx.x, bn = blockIdx.y;
    const int T = K >> 5;

    const __half* a0 = Ah + (size_t)bm * 128 * K;
    const __half* b0 = Bh + (size_t)bn * 128 * K;

    int g = lane >> 3, lr = lane & 7;
    uint32_t aoff = (uint32_t)((warpM*64 + (g&1)*8 + lr) * PSH + (g>>1)*8);
    uint32_t boff = (uint32_t)((warpN*32 + (g>>1)*8 + lr) * PSH + (g&1)*8);

    float acc[4][4][4];
#pragma unroll
    for (int i = 0; i < 4; i++)
#pragma unroll
        for (int j = 0; j < 4; j++)
#pragma unroll
            for (int r = 0; r < 4; r++) acc[i][j][r] = 0.f;

    stage_load(sbase, 0, a0, b0, K, 0, tid);
    stage_load(sbase, 1, a0, b0, K, 1, tid);
    stage_load(sbase, 2, a0, b0, K, 2, tid);

    for (int kt = 0; kt < T; kt++) {
        int rem = T - 1 - kt;
        if (rem >= 2)      asm volatile("cp.async.wait_group 2;" ::: "memory");
        else if (rem == 1) asm volatile("cp.async.wait_group 1;" ::: "memory");
        else               asm volatile("cp.async.wait_group 0;" ::: "memory");
        __syncthreads();
        if (kt + 3 < T) stage_load(sbase, (kt + 3) % NSTG, a0, b0, K, kt + 3, tid);

        uint32_t st = sbase + (uint32_t)(kt % NSTG) * (STG1 * 2);
        uint32_t sA = st, sB = st + TEN2*2;
#pragma unroll
        for (int ks = 0; ks < 2; ks++) {
            int kk = ks * 16;
            uint32_t ah[4][4], bh[4][2];
#pragma unroll
            for (int mi = 0; mi < 4; mi++)
                ldmx4(ah[mi], sA + (aoff + mi*16*PSH + kk) * 2);
#pragma unroll
            for (int p = 0; p < 2; p++) {
                uint32_t rh[4];
                ldmx4(rh, sB + (boff + p*16*PSH + kk) * 2);
                bh[2*p][0] = rh[0]; bh[2*p][1] = rh[1];
                bh[2*p+1][0] = rh[2]; bh[2*p+1][1] = rh[3];
            }
#pragma unroll
            for (int mi = 0; mi < 4; mi++)
#pragma unroll
                for (int ni = 0; ni < 4; ni++)
                    mma_f16(acc[mi][ni], ah[mi], bh[ni]);
        }
        __syncthreads();
    }

    int rr = lane >> 2, cc = (lane & 3) * 2;
#pragma unroll
    for (int mi = 0; mi < 4; mi++) {
        int row0 = bm * 128 + warpM * 64 + mi * 16 + rr;
#pragma unroll
        for (int ni = 0; ni < 4; ni++) {
            int col = bn * 128 + warpN * 32 + ni * 8 + cc;
            float2 v0 = make_float2(acc[mi][ni][0], acc[mi][ni][1]);
            float2 v1 = make_float2(acc[mi][ni][2], acc[mi][ni][3]);
            *(float2*)&C[(size_t)row0 * N + col]       = v0;
            *(float2*)&C[(size_t)(row0 + 8) * N + col] = v1;
        }
    }
}

// ------------- BA projection split-K -> partials -------------
__global__ void gemm_ba_part(const float* __restrict__ X, const float* __restrict__ W) {
    __shared__ float Xs[64][65];
    __shared__ float Ws[64][64];
    int tid = threadIdx.x;
    int row0 = blockIdx.x * 64;
    int kbase = blockIdx.y * 256;
    int col = (tid & 15) * 4;
    int r0 = (tid >> 4) * 4;
    float acc[4][4] = {};
    for (int k0 = kbase; k0 < kbase + 256; k0 += 64) {
#pragma unroll
        for (int j = 0; j < 16; j++) {
            int idx = j * 256 + tid;
            int r = idx >> 6, kk = idx & 63;
            Xs[r][kk] = X[(size_t)(row0 + r) * HID + k0 + kk];
        }
#pragma unroll
        for (int j = 0; j < 16; j++) {
            int idx = j * 256 + tid;
            int kk = idx >> 6, c = idx & 63;
            Ws[kk][c] = W[(size_t)(k0 + kk) * 64 + c];
        }
        __syncthreads();
#pragma unroll 8
        for (int kk = 0; kk < 64; kk++) {
            float4 b = *(float4*)&Ws[kk][col];
#pragma unroll
            for (int r = 0; r < 4; r++) {
                float a = Xs[r0 + r][kk];
                acc[r][0] += a*b.x; acc[r][1] += a*b.y; acc[r][2] += a*b.z; acc[r][3] += a*b.w;
            }
        }
        __syncthreads();
    }
    float* dst = g_bap + (size_t)blockIdx.y * BSz * 64;
#pragma unroll
    for (int r = 0; r < 4; r++)
        *(float4*)&dst[(size_t)(row0 + r0 + r) * 64 + col] =
            make_float4(acc[r][0], acc[r][1], acc[r][2], acc[r][3]);
}

// -------- conv + silu + l2norm + head transpose + gates (float4-vectorized) --------
__global__ void conv_gate(const float* __restrict__ cw, const float* __restrict__ dtb,
                          const float* __restrict__ Alog) {
    int bs = blockIdx.x;
    int b = bs / S_, s = bs % S_;
    int tid = threadIdx.x;
    __shared__ float cs[CONV_DIM];
    __shared__ float hsum[32];
    const float* base = g_qkvz + (size_t)bs * QKVZ_N;
    const float4* cw4 = (const float4*)cw;

    for (int c4 = tid; c4 < CONV_DIM / 4; c4 += 256) {
        int c = c4 * 4;
        float4 w0 = cw4[c + 0], w1 = cw4[c + 1], w2 = cw4[c + 2], w3 = cw4[c + 3];
        float4 x3 = *(const float4*)&base[c];
        float4 r;
        r.x = x3.x * w0.w; r.y = x3.y * w1.w; r.z = x3.z * w2.w; r.w = x3.w * w3.w;
        if (s >= 1) {
            float4 x2 = *(const float4*)&base[c - (size_t)QKVZ_N];
            r.x += x2.x * w0.z; r.y += x2.y * w1.z; r.z += x2.z * w2.z; r.w += x2.w * w3.z;
        }
        if (s >= 2) {
            float4 x1 = *(const float4*)&base[c - (size_t)2*QKVZ_N];
            r.x += x1.x * w0.y; r.y += x1.y * w1.y; r.z += x1.z * w2.y; r.w += x1.w * w3.y;
        }
        if (s >= 3) {
            float4 x0 = *(const float4*)&base[c - (size_t)3*QKVZ_N];
            r.x += x0.x * w0.x; r.y += x0.y * w1.x; r.z += x0.z * w2.x; r.w += x0.w * w3.x;
        }
        r.x = r.x / (1.f + __expf(-r.x));
        r.y = r.y / (1.f + __expf(-r.y));
        r.z = r.z / (1.f + __expf(-r.z));
        r.w = r.w / (1.f + __expf(-r.w));
        *(float4*)&cs[c] = r;
    }
    __syncthreads();
    int warp = tid >> 5, lane = tid & 31;
    for (int h = warp; h < 32; h += 8) {
        float ss = 0.f;
        for (int d = lane; d < 128; d += 32) { float v = cs[h*128 + d]; ss += v * v; }
#pragma unroll
        for (int o = 16; o; o >>= 1) ss += __shfl_xor_sync(~0u, ss, o);
        if (!lane) hsum[h] = rsqrtf(ss + 1e-6f);
    }
    __syncthreads();
    for (int c4 = tid; c4 < KEY_DIM / 4; c4 += 256) {
        int c = c4 * 4;
        int h = c >> 7, d = c & 127;
        float sc = hsum[h] * QSCALE;
        float4 v = *(float4*)&cs[c];
        v.x *= sc; v.y *= sc; v.z *= sc; v.w *= sc;
        *(float4*)&g_q[(((size_t)b*HKq + h)*S_ + s)*DKd + d] = v;
    }
    for (int c4 = tid; c4 < KEY_DIM / 4; c4 += 256) {
        int c = c4 * 4;
        int h = c >> 7, d = c & 127;
        float sc = hsum[16 + h];
        float4 v = *(float4*)&cs[KEY_DIM + c];
        v.x *= sc; v.y *= sc; v.z *= sc; v.w *= sc;
        *(float4*)&g_k[(((size_t)b*HKq + h)*S_ + s)*DKd + d] = v;
    }
    for (int c4 = tid; c4 < VALUE_DIM / 4; c4 += 256) {
        int c = c4 * 4;
        int h = c >> 7, d = c & 127;
        float4 v = *(float4*)&cs[2*KEY_DIM + c];
        *(float4*)&g_v[(((size_t)b*HVv + h)*S_ + s)*DVd + d] = v;
    }
    if (tid < 64) {
        float bb = 0.f;
#pragma unroll
        for (int p = 0; p < 8; p++) bb += g_bap[(size_t)p * BSz * 64 + (size_t)bs * 64 + tid];
        if (tid < 32) {
            g_beta[((size_t)b*HVv + tid)*S_ + s] = 1.f / (1.f + expf(-bb));
        } else {
            int h = tid - 32;
            float a = bb + dtb[h];
            float sp = (a > 20.f) ? a : log1pf(expf(a));
            g_g[((size_t)b*HVv + h)*S_ + s] = -expf(Alog[h]) * sp;
        }
    }
}

// -------- per-(b,h,chunk) intra-chunk quantities (register-tiled float4) --------
__global__ void __launch_bounds__(256, 1) chunk_prep() {
    extern __shared__ float sm[];
    float* q_s  = sm;
    float* k_s  = q_s  + 64*SW;
    float* vb_s = k_s  + 64*SW;
    float* A_s  = vb_s + 64*SW;
    float* T_s  = A_s  + 64*64;
    __shared__ float gc_s[64], beta_s[64], kbe_s[64];

    int blk = blockIdx.x;
    int n = blk & 31, h = (blk >> 5) & 31, b = blk >> 10;
    int hq = h >> 1;
    int tid = threadIdx.x;

    size_t qk_off = (((size_t)b*HKq + hq)*S_ + (size_t)n*CHUNK) * DKd;
    size_t v_off  = (((size_t)b*HVv + h )*S_ + (size_t)n*CHUNK) * DVd;
    size_t gb_off = ((size_t)b*HVv + h)*S_ + (size_t)n*CHUNK;

    if (tid < 64) { gc_s[tid] = g_g[gb_off + tid]; beta_s[tid] = g_beta[gb_off + tid]; }
    __syncthreads();
    if (tid == 0) { for (int i = 1; i < 64; i++) gc_s[i] += gc_s[i - 1]; }
    __syncthreads();
    if (tid < 64) {
        g_gc[gb_off + tid] = gc_s[tid];
        kbe_s[tid] = beta_s[tid] * expf(gc_s[tid]);
    }
    for (int idx = tid; idx < 2048; idx += 256) {
        int r = idx >> 5, d = (idx & 31) * 4;
        float4 qv = *(const float4*)&g_q[qk_off + (size_t)r*128 + d];
        float4 kv = *(const float4*)&g_k[qk_off + (size_t)r*128 + d];
        float4 vv = *(const float4*)&g_v[v_off  + (size_t)r*128 + d];
        float be = beta_s[r];
        vv.x *= be; vv.y *= be; vv.z *= be; vv.w *= be;
        *(float4*)&q_s [r*SW + d] = qv;
        *(float4*)&k_s [r*SW + d] = kv;
        *(float4*)&vb_s[r*SW + d] = vv;
    }
    __syncthreads();

    {
        int jt = tid & 15, ct = tid >> 4;
        int j0 = jt * 4, c0 = ct * 4;
        float aa[4][4] = {}, aq[4][4] = {};
        for (int dk = 0; dk < 128; dk += 4) {
            float4 kj[4], kc[4], qc[4];
#pragma unroll
            for (int x = 0; x < 4; x++) kj[x] = *(float4*)&k_s[(j0+x)*SW + dk];
#pragma unroll
            for (int x = 0; x < 4; x++) kc[x] = *(float4*)&k_s[(c0+x)*SW + dk];
#pragma unroll
            for (int x = 0; x < 4; x++) qc[x] = *(float4*)&q_s[(c0+x)*SW + dk];
#pragma unroll
            for (int ci = 0; ci < 4; ci++)
#pragma unroll
                for (int ji = 0; ji < 4; ji++) {
                    aa[ci][ji] += kc[ci].x*kj[ji].x + kc[ci].y*kj[ji].y
                                + kc[ci].z*kj[ji].z + kc[ci].w*kj[ji].w;
                    aq[ci][ji] += qc[ci].x*kj[ji].x + qc[ci].y*kj[ji].y
                                + qc[ci].z*kj[ji].z + qc[ci].w*kj[ji].w;
                }
        }
        size_t at_off = gb_off * CHUNK;
#pragma unroll
        for (int ci = 0; ci < 4; ci++)
#pragma unroll
            for (int ji = 0; ji < 4; ji++) {
                int c = c0 + ci, j = j0 + ji;
                float e = __expf(gc_s[c] - gc_s[j]);
                A_s[c*64 + j] = (j < c) ? aa[ci][ji] * beta_s[c] * e : 0.f;
                g_attn[at_off + c*64 + j] = (j <= c) ? aq[ci][ji] * e : 0.f;
            }
    }
    __syncthreads();

    if (tid < 64) {
        int col = tid;
        for (int c = 0; c < 64; c++) {
            float ssum = (c == col) ? 1.f : 0.f;
            for (int j = col; j < c; j++) ssum -= A_s[c*64 + j] * T_s[j*65 + col];
            T_s[c*65 + col] = (c >= col) ? ssum : 0.f;
        }
    }
    __syncthreads();

    {
        int ct8 = tid >> 5, lane = tid & 31;
        int c0 = ct8 * 8, d0 = lane * 4;
        float av[8][4] = {}, ak[8][4] = {};
        int jmax = c0 + 8;
        for (int j = 0; j < jmax; j++) {
            float4 vv = *(float4*)&vb_s[j*SW + d0];
            float4 kk = *(float4*)&k_s [j*SW + d0];
            float kb = kbe_s[j];
            kk.x *= kb; kk.y *= kb; kk.z *= kb; kk.w *= kb;
#pragma unroll
            for (int ci = 0; ci < 8; ci++) {
                float t = T_s[(c0+ci)*65 + j];
                av[ci][0] += t*vv.x; av[ci][1] += t*vv.y; av[ci][2] += t*vv.z; av[ci][3] += t*vv.w;
                ak[ci][0] += t*kk.x; ak[ci][1] += t*kk.y; ak[ci][2] += t*kk.z; ak[ci][3] += t*kk.w;
            }
        }
        size_t kcd_off = (((size_t)b*HVv + h)*S_ + (size_t)n*CHUNK) * DKd;
#pragma unroll
        for (int ci = 0; ci < 8; ci++) {
            *(float4*)&g_vadj[v_off  + (size_t)(c0+ci)*128 + d0] =
                make_float4(av[ci][0], av[ci][1], av[ci][2], av[ci][3]);
            *(float4*)&g_kcd [kcd_off + (size_t)(c0+ci)*128 + d0] =
                make_float4(ak[ci][0], ak[ci][1], ak[ci][2], ak[ci][3]);
        }
    }
}

// ======== HMMA scan: state_T fp32 [dv][dk]; per-chunk fp16 operand tiles ========
// grid (64 bh, 2 dvt), 512 threads (16 warps).
#define STF 132     // state_T fp32 row stride (floats)
#define SH6 136     // fp16 stride for [*][128] tiles (272B: conflict-free ldmatrix)
#define SH7 72      // fp16 stride for [*][64] tiles  (144B: conflict-free ldmatrix)

__global__ void __launch_bounds__(512, 1) scan_kernel() {
    extern __shared__ char smraw[];
    float*  stT  = (float*)smraw;                 // [64][STF]  state^T (dv, dk) fp32
    __half* st16 = (__half*)(stT + 64*STF);       // [64][SH6]  state^T fp16
    __half* kcd16= st16 + 64*SH6;                 // [64][SH6]  -kcd (c, dk)
    __half* q16  = kcd16 + 64*SH6;                // [64][SH6]  q (c, dk)
    __half* kT16 = q16 + 64*SH6;                  // [128][SH7] k^T (dk, c)
    __half* at16 = kT16 + 128*SH7;                // [64][SH7]  attn (c, j)
    __half* vnT16= at16 + 64*SH7;                 // [64][SH7]  vnew^T (dv, c)
    __half* vkT16= vnT16 + 64*SH7;                // [64][SH7]  vek^T (dv, c)
    __shared__ float eg_s[64], ek_s[64];

    int bh = blockIdx.x, dvt = blockIdx.y;
    int b = bh >> 5, h = bh & 31, hq = h >> 1;
    int tid = threadIdx.x, lane = tid & 31, wid = tid >> 5;

    int mW = (wid >> 2) * 16;          // c-tile base (M1/M2)
    int nW = (wid & 3) * 16;           // dv-tile base (M1/M2)
    int g = lane >> 3, lr = lane & 7;
    int rr = lane >> 2, cc = (lane & 3) * 2;

    for (int i = tid; i < 64*STF; i += 512) stT[i] = 0.f;
    for (int i = tid; i < 64*SH6; i += 512) st16[i] = __float2half(0.f);

    // ldmatrix base addresses (fixed per thread)
    uint32_t aKCD = smem_u32(kcd16) + 2u*((mW + (g&1)*8 + lr)*SH6 + (g>>1)*8);
    uint32_t aQ   = smem_u32(q16)   + 2u*((mW + (g&1)*8 + lr)*SH6 + (g>>1)*8);
    uint32_t aAT  = smem_u32(at16)  + 2u*((mW + (g&1)*8 + lr)*SH7 + (g>>1)*8);
    uint32_t bST  = smem_u32(st16)  + 2u*((nW + (g>>1)*8 + lr)*SH6 + (g&1)*8);
    uint32_t bVN  = smem_u32(vnT16) + 2u*((nW + (g>>1)*8 + lr)*SH7 + (g&1)*8);

    for (int n = 0; n < NCH; n++) {
        size_t qk_off = (((size_t)b*HKq + hq)*S_ + (size_t)n*CHUNK) * DKd;
        size_t kv_off = (((size_t)b*HVv + h )*S_ + (size_t)n*CHUNK) * DKd;
        size_t gb_off = ((size_t)b*HVv + h)*S_ + (size_t)n*CHUNK;

        __syncthreads();   // bar0: previous-chunk M3 stores / this chunk loads
        for (int idx = tid; idx < 2048; idx += 512) {
            int r = idx >> 5, d = (idx & 31) * 4;
            float4 kc = *(const float4*)&g_kcd[kv_off + (size_t)r*128 + d];
            float4 qv = *(const float4*)&g_q  [qk_off + (size_t)r*128 + d];
            float4 kv = *(const float4*)&g_k  [qk_off + (size_t)r*128 + d];
            *(__half2*)&kcd16[r*SH6 + d]     = __floats2half2_rn(-kc.x, -kc.y);
            *(__half2*)&kcd16[r*SH6 + d + 2] = __floats2half2_rn(-kc.z, -kc.w);
            *(__half2*)&q16[r*SH6 + d]       = __floats2half2_rn(qv.x, qv.y);
            *(__half2*)&q16[r*SH6 + d + 2]   = __floats2half2_rn(qv.z, qv.w);
            kT16[(d+0)*SH7 + r] = __float2half_rn(kv.x);
            kT16[(d+1)*SH7 + r] = __float2half_rn(kv.y);
            kT16[(d+2)*SH7 + r] = __float2half_rn(kv.z);
            kT16[(d+3)*SH7 + r] = __float2half_rn(kv.w);
        }
        for (int idx = tid; idx < 1024; idx += 512) {
            int c = idx >> 4, j = (idx & 15) * 4;
            float4 av = *(const float4*)&g_attn[gb_off*CHUNK + (size_t)c*64 + j];
            *(__half2*)&at16[c*SH7 + j]     = __floats2half2_rn(av.x, av.y);
            *(__half2*)&at16[c*SH7 + j + 2] = __floats2half2_rn(av.z, av.w);
        }
        if (tid < 64) {
            float gv = g_gc[gb_off + tid];
            float gl = g_gc[gb_off + 63];
            eg_s[tid] = expf(gv);
            ek_s[tid] = expf(gl - gv);
        }
        __syncthreads();   // bar1

        // ---- M1: vnew[c,dv] = vadj + (-kcd) @ state ----
        float c0[4], c1[4];
        {
            size_t vb = kv_off + (size_t)(mW + rr)*128 + dvt*64 + nW + cc;
            float2 t;
            t = *(const float2*)&g_vadj[vb];              c0[0]=t.x; c0[1]=t.y;
            t = *(const float2*)&g_vadj[vb + 8*128];      c0[2]=t.x; c0[3]=t.y;
            t = *(const float2*)&g_vadj[vb + 8];          c1[0]=t.x; c1[1]=t.y;
            t = *(const float2*)&g_vadj[vb + 8*128 + 8];  c1[2]=t.x; c1[3]=t.y;
        }
#pragma unroll
        for (int kt = 0; kt < 8; kt++) {
            uint32_t af[4], bf[4];
            ldmx4(af, aKCD + 2u*(kt*16));
            ldmx4(bf, bST  + 2u*(kt*16));
            mma_f16(c0, af, bf);
            mma_f16(c1, af, bf + 2);
        }
        {
            int cr0 = mW + rr, cr1 = mW + rr + 8;
            int d0 = nW + cc, d1 = nW + 8 + cc;
            float e0 = ek_s[cr0], e1 = ek_s[cr1];
            vnT16[(d0  )*SH7 + cr0] = __float2half_rn(c0[0]);
            vnT16[(d0+1)*SH7 + cr0] = __float2half_rn(c0[1]);
            vnT16[(d0  )*SH7 + cr1] = __float2half_rn(c0[2]);
            vnT16[(d0+1)*SH7 + cr1] = __float2half_rn(c0[3]);
            vnT16[(d1  )*SH7 + cr0] = __float2half_rn(c1[0]);
            vnT16[(d1+1)*SH7 + cr0] = __float2half_rn(c1[1]);
            vnT16[(d1  )*SH7 + cr1] = __float2half_rn(c1[2]);
            vnT16[(d1+1)*SH7 + cr1] = __float2half_rn(c1[3]);
            vkT16[(d0  )*SH7 + cr0] = __float2half_rn(c0[0]*e0);
            vkT16[(d0+1)*SH7 + cr0] = __float2half_rn(c0[1]*e0);
            vkT16[(d0  )*SH7 + cr1] = __float2half_rn(c0[2]*e1);
            vkT16[(d0+1)*SH7 + cr1] = __float2half_rn(c0[3]*e1);
            vkT16[(d1  )*SH7 + cr0] = __float2half_rn(c1[0]*e0);
            vkT16[(d1+1)*SH7 + cr0] = __float2half_rn(c1[1]*e0);
            vkT16[(d1  )*SH7 + cr1] = __float2half_rn(c1[2]*e1);
            vkT16[(d1+1)*SH7 + cr1] = __float2half_rn(c1[3]*e1);
        }
        __syncthreads();   // bar2

        // ---- M2: o = eg[c]*(q@state) + attn@vnew ----
        float o0[4] = {0,0,0,0}, o1[4] = {0,0,0,0};
#pragma unroll
        for (int kt = 0; kt < 8; kt++) {
            uint32_t af[4], bf[4];
            ldmx4(af, aQ  + 2u*(kt*16));
            ldmx4(bf, bST + 2u*(kt*16));
            mma_f16(o0, af, bf);
            mma_f16(o1, af, bf + 2);
        }
        {
            float e0 = eg_s[mW + rr], e1 = eg_s[mW + rr + 8];
            o0[0]*=e0; o0[1]*=e0; o0[2]*=e1; o0[3]*=e1;
            o1[0]*=e0; o1[1]*=e0; o1[2]*=e1; o1[3]*=e1;
        }
#pragma unroll
        for (int kt = 0; kt < 4; kt++) {
            uint32_t af[4], bf[4];
            ldmx4(af, aAT + 2u*(kt*16));
            ldmx4(bf, bVN + 2u*(kt*16));
            mma_f16(o0, af, bf);
            mma_f16(o1, af, bf + 2);
        }
        {
            size_t ob = ((size_t)b*S_ + (size_t)n*CHUNK + mW + rr)*VALUE_DIM
                      + (size_t)h*DVd + dvt*64 + nW + cc;
            *(float2*)&g_o[ob]                       = make_float2(o0[0], o0[1]);
            *(float2*)&g_o[ob + 8*(size_t)VALUE_DIM] = make_float2(o0[2], o0[3]);
            *(float2*)&g_o[ob + 8]                   = make_float2(o1[0], o1[1]);
            *(float2*)&g_o[ob + 8*(size_t)VALUE_DIM + 8] = make_float2(o1[2], o1[3]);
        }
        __syncthreads();   // bar3: M2a reads of st16 done before M3 overwrites

        // ---- M3: state_T[dv,dk] = egl*state_T + vek^T @ k ----
        float egl = eg_s[63];
#pragma unroll
        for (int i = 0; i < 2; i++) {
            int t = wid * 2 + i;
            int dv0 = (t >> 3) * 16, dk0 = (t & 7) * 16;
            float s0[4], s1[4];
            float* sp  = &stT[(dv0 + rr)*STF + dk0 + cc];
            float* sp8 = &stT[(dv0 + rr + 8)*STF + dk0 + cc];
            s0[0] = sp[0]*egl;  s0[1] = sp[1]*egl;
            s1[0] = sp[8]*egl;  s1[1] = sp[9]*egl;
            s0[2] = sp8[0]*egl; s0[3] = sp8[1]*egl;
            s1[2] = sp8[8]*egl; s1[3] = sp8[9]*egl;
            uint32_t aV = smem_u32(vkT16) + 2u*((dv0 + (g&1)*8 + lr)*SH7 + (g>>1)*8);
            uint32_t bK = smem_u32(kT16)  + 2u*((dk0 + (g>>1)*8 + lr)*SH7 + (g&1)*8);
#pragma unroll
            for (int kt = 0; kt < 4; kt++) {
                uint32_t af[4], bf[4];
                ldmx4(af, aV + 2u*(kt*16));
                ldmx4(bf, bK + 2u*(kt*16));
                mma_f16(s0, af, bf);
                mma_f16(s1, af, bf + 2);
            }
            sp[0]=s0[0];  sp[1]=s0[1];  sp[8]=s1[0];  sp[9]=s1[1];
            sp8[0]=s0[2]; sp8[1]=s0[3]; sp8[8]=s1[2]; sp8[9]=s1[3];
            *(__half2*)&st16[(dv0+rr)*SH6 + dk0 + cc]       = __floats2half2_rn(s0[0], s0[1]);
            *(__half2*)&st16[(dv0+rr)*SH6 + dk0 + 8 + cc]   = __floats2half2_rn(s1[0], s1[1]);
            *(__half2*)&st16[(dv0+rr+8)*SH6 + dk0 + cc]     = __floats2half2_rn(s0[2], s0[3]);
            *(__half2*)&st16[(dv0+rr+8)*SH6 + dk0 + 8 + cc] = __floats2half2_rn(s1[2], s1[3]);
        }
    }
}

// -------- gated RMSNorm -> fp16 directly into GEMM2 A buffer --------
__global__ void gated_norm(const float* __restrict__ nw) {
    int bs = blockIdx.x;
    int warp = threadIdx.x >> 5, lane = threadIdx.x & 31;
    for (int h = warp; h < HVv; h += 8) {
        size_t off = (size_t)bs * VALUE_DIM + (size_t)h * DVd;
        float4 v = ((float4*)(g_o + off))[lane];
        float ss = v.x*v.x + v.y*v.y + v.z*v.z + v.w*v.w;
#pragma unroll
        for (int o = 16; o; o >>= 1) ss += __shfl_xor_sync(~0u, ss, o);
        float r = rsqrtf(ss / 128.f + 1e-6f);
        size_t zoff = (size_t)bs * QKVZ_N + 2*KEY_DIM + VALUE_DIM + (size_t)h * DVd;
        float4 z = ((const float4*)(g_qkvz + zoff))[lane];
        float4 w = ((const float4*)nw)[lane];
        float r0 = v.x * r * w.x * (z.x / (1.f + expf(-z.x)));
        float r1 = v.y * r * w.y * (z.y / (1.f + expf(-z.y)));
        float r2 = v.z * r * w.z * (z.z / (1.f + expf(-z.z)));
        float r3 = v.w * r * w.w * (z.w / (1.f + expf(-z.w)));
        __half2 h0 = __floats2half2_rn(r0, r1);
        __half2 h1 = __floats2half2_rn(r2, r3);
        uint2 hv; hv.x = *(uint32_t*)&h0; hv.y = *(uint32_t*)&h1;
        ((uint2*)(g_r + off))[lane] = hv;
    }
}

// ---------------- launcher (single stream) ----------------
extern "C" void kernel_launch(void* const* d_in, const int* in_sizes, int n_in,
                              void* d_out, int out_size) {
    const float* hidden = (const float*)d_in[0];
    const float* Wqkvz  = (const float*)d_in[1];
    const float* Wba    = (const float*)d_in[2];
    const float* convw  = (const float*)d_in[3];
    const float* dtb    = (const float*)d_in[4];
    const float* Alog   = (const float*)d_in[5];
    const float* nw     = (const float*)d_in[6];
    const float* Wout   = (const float*)d_in[7];
    float* out = (float*)d_out;

    float *qkvz_p;
    __half *p_p, *r_p;
    cudaGetSymbolAddress((void**)&qkvz_p, g_qkvz);
    cudaGetSymbolAddress((void**)&p_p, g_p);
    cudaGetSymbolAddress((void**)&r_p, g_r);

    const int SMEM3 = (3*64*SW + 64*64 + 64*65) * 4;
    const int SMEM4 = 64*STF*4 + (3*64*SH6 + 128*SH7 + 3*64*SH7) * 2;  // 132096
    const int SMEM_MM = NSTG * STG1 * 2;
    cudaFuncSetAttribute(chunk_prep, cudaFuncAttributeMaxDynamicSharedMemorySize, SMEM3);
    cudaFuncSetAttribute(scan_kernel, cudaFuncAttributeMaxDynamicSharedMemorySize, SMEM4);
    cudaFuncSetAttribute(mmgemm, cudaFuncAttributeMaxDynamicSharedMemorySize, SMEM_MM);

    // --- GEMM1: qkvz = hidden @ W_qkvz ---
    cvt_h<<<(BSz*(size_t)HID)/1024, 256>>>(hidden, p_p);
    cvt_T<<<dim3(QKVZ_N/32, HID/32), dim3(32,8)>>>(Wqkvz, r_p, HID, QKVZ_N);
    mmgemm<<<dim3(BSz/128, QKVZ_N/128), 256, SMEM_MM>>>(p_p, r_p, qkvz_p, BSz, QKVZ_N, HID);

    // --- BA projection (split-K; reduce fused into conv_gate) ---
    gemm_ba_part<<<dim3(BSz/64, 8), 256>>>(hidden, Wba);

    // --- conv + gates, chunk prep, scan (HMMA), norm ---
    conv_gate<<<BSz, 256>>>(convw, dtb, Alog);
    chunk_prep<<<B_*HVv*NCH, 256, SMEM3>>>();
    scan_kernel<<<dim3(B_*HVv, 2), 512, SMEM4>>>();
    gated_norm<<<BSz, 256>>>(nw);

    // --- GEMM2: out = o @ W_out (A written fp16 by gated_norm) ---
    cvt_T<<<dim3(HID/32, VALUE_DIM/32), dim3(32,8)>>>(Wout, p_p, VALUE_DIM, HID);
    mmgemm<<<dim3(BSz/128, HID/128), 256, SMEM_MM>>>(r_p, p_p, out, BSz, HID, VALUE_DIM);
}

// round 13
// speedup vs baseline: 1.4920x; 1.0740x over previous
#include <cuda_runtime.h>
#include <cuda_bf16.h>
#include <cuda_fp16.h>
#include <math.h>
#include <stdint.h>

// ---------------- problem constants ----------------
#define B_   2
#define S_   2048
#define HID  2048
#define HKq  16
#define HVv  32
#define DKd  128
#define DVd  128
#define KC   4
#define CHUNK 64
#define NCH  (S_/CHUNK)          // 32
#define KEY_DIM 2048
#define VALUE_DIM 4096
#define CONV_DIM 8192
#define QKVZ_N 12288
#define BSz  (B_*S_)             // 4096
#define QSCALE 0.08838834764831845f   // DK^-0.5
#define SW 132                   // float4-aligned, conflict-free smem row stride
#define STF 132                  // state_T fp32 row stride (floats)
#define SH6 136                  // fp16 stride for [*][128] tiles (conflict-free ldmatrix)
#define SH7 72                   // fp16 stride for [*][64] tiles

// ---------------- scratch (static device memory; no allocations) ------------
__device__ float g_qkvz[(size_t)BSz*QKVZ_N];               // [BS,12288] q|k|v|z
__device__ float g_bap[(size_t)8*BSz*64];                  // split-K partials
__device__ float g_q[(size_t)B_*HKq*S_*DKd];
__device__ float g_k[(size_t)B_*HKq*S_*DKd];
__device__ float g_v[(size_t)B_*HVv*S_*DVd];
__device__ float g_g[(size_t)B_*HVv*S_];
__device__ float g_beta[(size_t)B_*HVv*S_];
__device__ float g_gc[(size_t)B_*HVv*S_];
__device__ float g_vadj[(size_t)B_*HVv*S_*DVd];
__device__ float g_kcd[(size_t)B_*HVv*S_*DKd];
__device__ float g_attn[(size_t)B_*HVv*S_*CHUNK];
__device__ float g_o[(size_t)BSz*VALUE_DIM];

// fp16 operand buffers
__device__ __half g_p [(size_t)8388608];    // A1 (hidden) / B2t (Wout^T)
__device__ __half g_r [(size_t)25165824];   // B1t (Wqkvz^T) ; later A2 (gated_norm out)

__device__ __forceinline__ uint32_t smem_u32(const void* p) {
    uint32_t a;
    asm("{ .reg .u64 t; cvta.to.shared.u64 t, %1; cvt.u32.u64 %0, t; }" : "=r"(a) : "l"(p));
    return a;
}

// ---------------- fp32 -> fp16 (elementwise, float4) ----------------
__global__ void cvt_h(const float* __restrict__ X, __half* __restrict__ H) {
    size_t i = ((size_t)blockIdx.x * 256 + threadIdx.x) * 4;
    float4 v = *(const float4*)&X[i];
    __half2 h0 = __floats2half2_rn(v.x, v.y);
    __half2 h1 = __floats2half2_rn(v.z, v.w);
    uint2 hv;
    hv.x = *(uint32_t*)&h0; hv.y = *(uint32_t*)&h1;
    *(uint2*)&H[i] = hv;
}

// ---------------- fp32 [K,N] -> fp16 [N,K] transpose ----------------
__global__ void cvt_T(const float* __restrict__ W, __half* __restrict__ Ht, int K, int N) {
    __shared__ float tile[32][33];
    int n0 = blockIdx.x * 32, k0 = blockIdx.y * 32;
    int tx = threadIdx.x, ty = threadIdx.y;   // 32 x 8
#pragma unroll
    for (int j = 0; j < 32; j += 8)
        tile[ty + j][tx] = W[(size_t)(k0 + ty + j) * N + n0 + tx];
    __syncthreads();
#pragma unroll
    for (int j = 0; j < 32; j += 8)
        Ht[(size_t)(n0 + ty + j) * K + k0 + tx] = __float2half_rn(tile[tx][ty + j]);
}

// ============ fp16 HMMA GEMM: C[M,N] = A[M,K] @ Bt[N,K]^T (fp32 accum) ============
#define PSH 40
#define TEN2 (128*PSH)
#define STG1 (2*TEN2)
#define NSTG 4

__device__ __forceinline__ void mma_f16(float* c, const uint32_t* a, const uint32_t* b) {
    asm volatile("mma.sync.aligned.m16n8k16.row.col.f32.f16.f16.f32 "
                 "{%0,%1,%2,%3}, {%4,%5,%6,%7}, {%8,%9}, {%0,%1,%2,%3};"
                 : "+f"(c[0]), "+f"(c[1]), "+f"(c[2]), "+f"(c[3])
                 : "r"(a[0]), "r"(a[1]), "r"(a[2]), "r"(a[3]), "r"(b[0]), "r"(b[1]));
}
__device__ __forceinline__ void ldmx4(uint32_t* r, uint32_t addr) {
    asm volatile("ldmatrix.sync.aligned.m8n8.x4.shared.b16 {%0,%1,%2,%3}, [%4];"
                 : "=r"(r[0]), "=r"(r[1]), "=r"(r[2]), "=r"(r[3]) : "r"(addr));
}

__device__ __forceinline__ void stage_load(uint32_t sbase_b, int stage,
    const __half* a0, const __half* b0, int K, int kt, int tid)
{
    const __half* gp[2] = {a0, b0};
    uint32_t st_b = sbase_b + (uint32_t)stage * (STG1 * 2);
#pragma unroll
    for (int t = 0; t < 2; t++) {
        uint32_t tb = st_b + (uint32_t)t * (TEN2 * 2);
#pragma unroll
        for (int j = 0; j < 2; j++) {
            int idx = j * 256 + tid;
            int row = idx >> 2, c16 = idx & 3;
            uint32_t sa = tb + (uint32_t)(row * (PSH*2) + c16 * 16);
            const void* ga = gp[t] + (size_t)row * K + (size_t)kt * 32 + c16 * 8;
            asm volatile("cp.async.cg.shared.global [%0], [%1], 16;" :: "r"(sa), "l"(ga));
        }
    }
    asm volatile("cp.async.commit_group;" ::: "memory");
}

__global__ void __launch_bounds__(256, 2) mmgemm(
    const __half* __restrict__ Ah, const __half* __restrict__ Bh,
    float* __restrict__ C, int M, int N, int K)
{
    extern __shared__ __half smem[];
    uint32_t sbase = smem_u32(smem);
    int tid = threadIdx.x, lane = tid & 31, wid = tid >> 5;
    int warpM = wid >> 2, warpN = wid & 3;
    int bm = blockIdx.x, bn = blockIdx.y;
    const int T = K >> 5;

    const __half* a0 = Ah + (size_t)bm * 128 * K;
    const __half* b0 = Bh + (size_t)bn * 128 * K;

    int g = lane >> 3, lr = lane & 7;
    uint32_t aoff = (uint32_t)((warpM*64 + (g&1)*8 + lr) * PSH + (g>>1)*8);
    uint32_t boff = (uint32_t)((warpN*32 + (g>>1)*8 + lr) * PSH + (g&1)*8);

    float acc[4][4][4];
#pragma unroll
    for (int i = 0; i < 4; i++)
#pragma unroll
        for (int j = 0; j < 4; j++)
#pragma unroll
            for (int r = 0; r < 4; r++) acc[i][j][r] = 0.f;

    stage_load(sbase, 0, a0, b0, K, 0, tid);
    stage_load(sbase, 1, a0, b0, K, 1, tid);
    stage_load(sbase, 2, a0, b0, K, 2, tid);

    for (int kt = 0; kt < T; kt++) {
        int rem = T - 1 - kt;
        if (rem >= 2)      asm volatile("cp.async.wait_group 2;" ::: "memory");
        else if (rem == 1) asm volatile("cp.async.wait_group 1;" ::: "memory");
        else               asm volatile("cp.async.wait_group 0;" ::: "memory");
        __syncthreads();
        if (kt + 3 < T) stage_load(sbase, (kt + 3) % NSTG, a0, b0, K, kt + 3, tid);

        uint32_t st = sbase + (uint32_t)(kt % NSTG) * (STG1 * 2);
        uint32_t sA = st, sB = st + TEN2*2;
#pragma unroll
        for (int ks = 0; ks < 2; ks++) {
            int kk = ks * 16;
            uint32_t ah[4][4], bh[4][2];
#pragma unroll
            for (int mi = 0; mi < 4; mi++)
                ldmx4(ah[mi], sA + (aoff + mi*16*PSH + kk) * 2);
#pragma unroll
            for (int p = 0; p < 2; p++) {
                uint32_t rh[4];
                ldmx4(rh, sB + (boff + p*16*PSH + kk) * 2);
                bh[2*p][0] = rh[0]; bh[2*p][1] = rh[1];
                bh[2*p+1][0] = rh[2]; bh[2*p+1][1] = rh[3];
            }
#pragma unroll
            for (int mi = 0; mi < 4; mi++)
#pragma unroll
                for (int ni = 0; ni < 4; ni++)
                    mma_f16(acc[mi][ni], ah[mi], bh[ni]);
        }
        __syncthreads();
    }

    int rr = lane >> 2, cc = (lane & 3) * 2;
#pragma unroll
    for (int mi = 0; mi < 4; mi++) {
        int row0 = bm * 128 + warpM * 64 + mi * 16 + rr;
#pragma unroll
        for (int ni = 0; ni < 4; ni++) {
            int col = bn * 128 + warpN * 32 + ni * 8 + cc;
            float2 v0 = make_float2(acc[mi][ni][0], acc[mi][ni][1]);
            float2 v1 = make_float2(acc[mi][ni][2], acc[mi][ni][3]);
            *(float2*)&C[(size_t)row0 * N + col]       = v0;
            *(float2*)&C[(size_t)(row0 + 8) * N + col] = v1;
        }
    }
}

// ------------- BA projection split-K -> partials -------------
__global__ void gemm_ba_part(const float* __restrict__ X, const float* __restrict__ W) {
    __shared__ float Xs[64][65];
    __shared__ float Ws[64][64];
    int tid = threadIdx.x;
    int row0 = blockIdx.x * 64;
    int kbase = blockIdx.y * 256;
    int col = (tid & 15) * 4;
    int r0 = (tid >> 4) * 4;
    float acc[4][4] = {};
    for (int k0 = kbase; k0 < kbase + 256; k0 += 64) {
#pragma unroll
        for (int j = 0; j < 16; j++) {
            int idx = j * 256 + tid;
            int r = idx >> 6, kk = idx & 63;
            Xs[r][kk] = X[(size_t)(row0 + r) * HID + k0 + kk];
        }
#pragma unroll
        for (int j = 0; j < 16; j++) {
            int idx = j * 256 + tid;
            int kk = idx >> 6, c = idx & 63;
            Ws[kk][c] = W[(size_t)(k0 + kk) * 64 + c];
        }
        __syncthreads();
#pragma unroll 8
        for (int kk = 0; kk < 64; kk++) {
            float4 b = *(float4*)&Ws[kk][col];
#pragma unroll
            for (int r = 0; r < 4; r++) {
                float a = Xs[r0 + r][kk];
                acc[r][0] += a*b.x; acc[r][1] += a*b.y; acc[r][2] += a*b.z; acc[r][3] += a*b.w;
            }
        }
        __syncthreads();
    }
    float* dst = g_bap + (size_t)blockIdx.y * BSz * 64;
#pragma unroll
    for (int r = 0; r < 4; r++)
        *(float4*)&dst[(size_t)(row0 + r0 + r) * 64 + col] =
            make_float4(acc[r][0], acc[r][1], acc[r][2], acc[r][3]);
}

// -------- conv + silu + l2norm + head transpose + gates (float4-vectorized) --------
__global__ void conv_gate(const float* __restrict__ cw, const float* __restrict__ dtb,
                          const float* __restrict__ Alog) {
    int bs = blockIdx.x;
    int b = bs / S_, s = bs % S_;
    int tid = threadIdx.x;
    __shared__ float cs[CONV_DIM];
    __shared__ float hsum[32];
    const float* base = g_qkvz + (size_t)bs * QKVZ_N;
    const float4* cw4 = (const float4*)cw;

    for (int c4 = tid; c4 < CONV_DIM / 4; c4 += 256) {
        int c = c4 * 4;
        float4 w0 = cw4[c + 0], w1 = cw4[c + 1], w2 = cw4[c + 2], w3 = cw4[c + 3];
        float4 x3 = *(const float4*)&base[c];
        float4 r;
        r.x = x3.x * w0.w; r.y = x3.y * w1.w; r.z = x3.z * w2.w; r.w = x3.w * w3.w;
        if (s >= 1) {
            float4 x2 = *(const float4*)&base[c - (size_t)QKVZ_N];
            r.x += x2.x * w0.z; r.y += x2.y * w1.z; r.z += x2.z * w2.z; r.w += x2.w * w3.z;
        }
        if (s >= 2) {
            float4 x1 = *(const float4*)&base[c - (size_t)2*QKVZ_N];
            r.x += x1.x * w0.y; r.y += x1.y * w1.y; r.z += x1.z * w2.y; r.w += x1.w * w3.y;
        }
        if (s >= 3) {
            float4 x0 = *(const float4*)&base[c - (size_t)3*QKVZ_N];
            r.x += x0.x * w0.x; r.y += x0.y * w1.x; r.z += x0.z * w2.x; r.w += x0.w * w3.x;
        }
        r.x = r.x / (1.f + __expf(-r.x));
        r.y = r.y / (1.f + __expf(-r.y));
        r.z = r.z / (1.f + __expf(-r.z));
        r.w = r.w / (1.f + __expf(-r.w));
        *(float4*)&cs[c] = r;
    }
    __syncthreads();
    int warp = tid >> 5, lane = tid & 31;
    for (int h = warp; h < 32; h += 8) {
        float ss = 0.f;
        for (int d = lane; d < 128; d += 32) { float v = cs[h*128 + d]; ss += v * v; }
#pragma unroll
        for (int o = 16; o; o >>= 1) ss += __shfl_xor_sync(~0u, ss, o);
        if (!lane) hsum[h] = rsqrtf(ss + 1e-6f);
    }
    __syncthreads();
    for (int c4 = tid; c4 < KEY_DIM / 4; c4 += 256) {
        int c = c4 * 4;
        int h = c >> 7, d = c & 127;
        float sc = hsum[h] * QSCALE;
        float4 v = *(float4*)&cs[c];
        v.x *= sc; v.y *= sc; v.z *= sc; v.w *= sc;
        *(float4*)&g_q[(((size_t)b*HKq + h)*S_ + s)*DKd + d] = v;
    }
    for (int c4 = tid; c4 < KEY_DIM / 4; c4 += 256) {
        int c = c4 * 4;
        int h = c >> 7, d = c & 127;
        float sc = hsum[16 + h];
        float4 v = *(float4*)&cs[KEY_DIM + c];
        v.x *= sc; v.y *= sc; v.z *= sc; v.w *= sc;
        *(float4*)&g_k[(((size_t)b*HKq + h)*S_ + s)*DKd + d] = v;
    }
    for (int c4 = tid; c4 < VALUE_DIM / 4; c4 += 256) {
        int c = c4 * 4;
        int h = c >> 7, d = c & 127;
        float4 v = *(float4*)&cs[2*KEY_DIM + c];
        *(float4*)&g_v[(((size_t)b*HVv + h)*S_ + s)*DVd + d] = v;
    }
    if (tid < 64) {
        float bb = 0.f;
#pragma unroll
        for (int p = 0; p < 8; p++) bb += g_bap[(size_t)p * BSz * 64 + (size_t)bs * 64 + tid];
        if (tid < 32) {
            g_beta[((size_t)b*HVv + tid)*S_ + s] = 1.f / (1.f + expf(-bb));
        } else {
            int h = tid - 32;
            float a = bb + dtb[h];
            float sp = (a > 20.f) ? a : log1pf(expf(a));
            g_g[((size_t)b*HVv + h)*S_ + s] = -expf(Alog[h]) * sp;
        }
    }
}

// ======== chunk_prep: grid (b*hq*n)=1024; HMMA dots shared across head pair ========
__global__ void __launch_bounds__(256, 1) chunk_prep() {
    extern __shared__ char smraw[];
    float* k_s   = (float*)smraw;              // [64][SW]
    float* vb_s  = k_s + 64*SW;                // [64][SW]
    float* dotsA = vb_s + 64*SW;               // [64*64] k.k
    float* dotsQ = dotsA + 4096;               // [64*64] q.k
    float* A_s   = dotsQ + 4096;               // [64*64]
    float* T_s   = A_s + 4096;                 // [64*65]
    __half* k16  = (__half*)(T_s + 64*65);     // [64][SH6]
    __half* q16  = k16 + 64*SH6;               // [64][SH6]
    __shared__ float gc_s[64], beta_s[64], kbe_s[64];

    int blk = blockIdx.x;
    int n = blk & 31, hq = (blk >> 5) & 15, b = blk >> 9;
    int tid = threadIdx.x, lane = tid & 31, wid = tid >> 5;

    size_t qk_off = (((size_t)b*HKq + hq)*S_ + (size_t)n*CHUNK) * DKd;

    // load q,k once (fp32 k for T products, fp16 q/k for dots)
    for (int idx = tid; idx < 2048; idx += 256) {
        int r = idx >> 5, d = (idx & 31) * 4;
        float4 qv = *(const float4*)&g_q[qk_off + (size_t)r*128 + d];
        float4 kv = *(const float4*)&g_k[qk_off + (size_t)r*128 + d];
        *(float4*)&k_s[r*SW + d] = kv;
        *(__half2*)&q16[r*SH6 + d]     = __floats2half2_rn(qv.x, qv.y);
        *(__half2*)&q16[r*SH6 + d + 2] = __floats2half2_rn(qv.z, qv.w);
        *(__half2*)&k16[r*SH6 + d]     = __floats2half2_rn(kv.x, kv.y);
        *(__half2*)&k16[r*SH6 + d + 2] = __floats2half2_rn(kv.z, kv.w);
    }
    __syncthreads();

    // HMMA dots: dotsA = k @ k^T, dotsQ = q @ k^T. Warp grid 4(m16) x 2(n32).
    {
        int mW = (wid >> 1) * 16, nW = (wid & 1) * 32;
        int g = lane >> 3, lr = lane & 7;
        uint32_t aK = smem_u32(k16) + 2u*(uint32_t)((mW + (g&1)*8 + lr)*SH6 + (g>>1)*8);
        uint32_t aQ = smem_u32(q16) + 2u*(uint32_t)((mW + (g&1)*8 + lr)*SH6 + (g>>1)*8);
        uint32_t bK = smem_u32(k16) + 2u*(uint32_t)((nW + (g>>1)*8 + lr)*SH6 + (g&1)*8);
        float accK[4][4], accQ[4][4];
#pragma unroll
        for (int i = 0; i < 4; i++)
#pragma unroll
            for (int r = 0; r < 4; r++) { accK[i][r] = 0.f; accQ[i][r] = 0.f; }
#pragma unroll
        for (int kt = 0; kt < 8; kt++) {
            uint32_t afk[4], afq[4], b0[4], b1[4];
            ldmx4(afk, aK + 2u*(kt*16));
            ldmx4(afq, aQ + 2u*(kt*16));
            ldmx4(b0, bK + 2u*(kt*16));
            ldmx4(b1, bK + 2u*(16*SH6 + kt*16));
            mma_f16(accK[0], afk, b0); mma_f16(accK[1], afk, b0 + 2);
            mma_f16(accK[2], afk, b1); mma_f16(accK[3], afk, b1 + 2);
            mma_f16(accQ[0], afq, b0); mma_f16(accQ[1], afq, b0 + 2);
            mma_f16(accQ[2], afq, b1); mma_f16(accQ[3], afq, b1 + 2);
        }
        int rr = lane >> 2, cc = (lane & 3) * 2;
#pragma unroll
        for (int ni = 0; ni < 4; ni++) {
            int j = nW + ni*8 + cc;
            int c0r = mW + rr;
            *(float2*)&dotsA[c0r*64 + j]     = make_float2(accK[ni][0], accK[ni][1]);
            *(float2*)&dotsA[(c0r+8)*64 + j] = make_float2(accK[ni][2], accK[ni][3]);
            *(float2*)&dotsQ[c0r*64 + j]     = make_float2(accQ[ni][0], accQ[ni][1]);
            *(float2*)&dotsQ[(c0r+8)*64 + j] = make_float2(accQ[ni][2], accQ[ni][3]);
        }
    }
    __syncthreads();

    // per v-head (pair shares q/k)
#pragma unroll 1
    for (int h2 = 0; h2 < 2; h2++) {
        int h = hq * 2 + h2;
        size_t v_off  = (((size_t)b*HVv + h)*S_ + (size_t)n*CHUNK) * DVd;
        size_t gb_off = ((size_t)b*HVv + h)*S_ + (size_t)n*CHUNK;

        if (tid < 64) { gc_s[tid] = g_g[gb_off + tid]; beta_s[tid] = g_beta[gb_off + tid]; }
        __syncthreads();
        if (tid == 0) { for (int i = 1; i < 64; i++) gc_s[i] += gc_s[i - 1]; }
        __syncthreads();
        if (tid < 64) {
            g_gc[gb_off + tid] = gc_s[tid];
            kbe_s[tid] = beta_s[tid] * expf(gc_s[tid]);
        }
        for (int idx = tid; idx < 2048; idx += 256) {
            int r = idx >> 5, d = (idx & 31) * 4;
            float4 vv = *(const float4*)&g_v[v_off + (size_t)r*128 + d];
            float be = beta_s[r];
            vv.x *= be; vv.y *= be; vv.z *= be; vv.w *= be;
            *(float4*)&vb_s[r*SW + d] = vv;
        }
        __syncthreads();

        size_t at_off = gb_off * CHUNK;
        for (int i = tid; i < 4096; i += 256) {
            int c = i >> 6, j = i & 63;
            float e = __expf(gc_s[c] - gc_s[j]);
            A_s[i] = (j < c) ? dotsA[i] * beta_s[c] * e : 0.f;
            g_attn[at_off + i] = (j <= c) ? dotsQ[i] * e : 0.f;
        }
        __syncthreads();

        if (tid < 64) {
            int col = tid;
            for (int c = 0; c < 64; c++) {
                float ssum = (c == col) ? 1.f : 0.f;
                for (int j = col; j < c; j++) ssum -= A_s[c*64 + j] * T_s[j*65 + col];
                T_s[c*65 + col] = (c >= col) ? ssum : 0.f;
            }
        }
        __syncthreads();

        {
            int ct8 = tid >> 5, lane2 = tid & 31;
            int c0 = ct8 * 8, d0 = lane2 * 4;
            float av[8][4] = {}, ak[8][4] = {};
            int jmax = c0 + 8;
            for (int j = 0; j < jmax; j++) {
                float4 vv = *(float4*)&vb_s[j*SW + d0];
                float4 kk = *(float4*)&k_s [j*SW + d0];
                float kb = kbe_s[j];
                kk.x *= kb; kk.y *= kb; kk.z *= kb; kk.w *= kb;
#pragma unroll
                for (int ci = 0; ci < 8; ci++) {
                    float t = T_s[(c0+ci)*65 + j];
                    av[ci][0] += t*vv.x; av[ci][1] += t*vv.y; av[ci][2] += t*vv.z; av[ci][3] += t*vv.w;
                    ak[ci][0] += t*kk.x; ak[ci][1] += t*kk.y; ak[ci][2] += t*kk.z; ak[ci][3] += t*kk.w;
                }
            }
            size_t kcd_off = gb_off * DKd;
#pragma unroll
            for (int ci = 0; ci < 8; ci++) {
                *(float4*)&g_vadj[v_off   + (size_t)(c0+ci)*128 + d0] =
                    make_float4(av[ci][0], av[ci][1], av[ci][2], av[ci][3]);
                *(float4*)&g_kcd [kcd_off + (size_t)(c0+ci)*128 + d0] =
                    make_float4(ak[ci][0], ak[ci][1], ak[ci][2], ak[ci][3]);
            }
        }
        __syncthreads();
    }
}

// ======== HMMA scan: state_T fp32 [dv][dk]; per-chunk fp16 operand tiles ========
__global__ void __launch_bounds__(512, 1) scan_kernel() {
    extern __shared__ char smraw[];
    float*  stT  = (float*)smraw;                 // [64][STF]  state^T (dv, dk) fp32
    __half* st16 = (__half*)(stT + 64*STF);       // [64][SH6]  state^T fp16
    __half* kcd16= st16 + 64*SH6;                 // [64][SH6]  -kcd (c, dk)
    __half* q16  = kcd16 + 64*SH6;                // [64][SH6]  q (c, dk)
    __half* kT16 = q16 + 64*SH6;                  // [128][SH7] k^T (dk, c)
    __half* at16 = kT16 + 128*SH7;                // [64][SH7]  attn (c, j)
    __half* vnT16= at16 + 64*SH7;                 // [64][SH7]  vnew^T (dv, c)
    __half* vkT16= vnT16 + 64*SH7;                // [64][SH7]  vek^T (dv, c)
    __shared__ float eg_s[64], ek_s[64];

    int bh = blockIdx.x, dvt = blockIdx.y;
    int b = bh >> 5, h = bh & 31, hq = h >> 1;
    int tid = threadIdx.x, lane = tid & 31, wid = tid >> 5;

    int mW = (wid >> 2) * 16;
    int nW = (wid & 3) * 16;
    int g = lane >> 3, lr = lane & 7;
    int rr = lane >> 2, cc = (lane & 3) * 2;

    for (int i = tid; i < 64*STF; i += 512) stT[i] = 0.f;
    for (int i = tid; i < 64*SH6; i += 512) st16[i] = __float2half(0.f);

    uint32_t aKCD = smem_u32(kcd16) + 2u*((mW + (g&1)*8 + lr)*SH6 + (g>>1)*8);
    uint32_t aQ   = smem_u32(q16)   + 2u*((mW + (g&1)*8 + lr)*SH6 + (g>>1)*8);
    uint32_t aAT  = smem_u32(at16)  + 2u*((mW + (g&1)*8 + lr)*SH7 + (g>>1)*8);
    uint32_t bST  = smem_u32(st16)  + 2u*((nW + (g>>1)*8 + lr)*SH6 + (g&1)*8);
    uint32_t bVN  = smem_u32(vnT16) + 2u*((nW + (g>>1)*8 + lr)*SH7 + (g&1)*8);

    for (int n = 0; n < NCH; n++) {
        size_t qk_off = (((size_t)b*HKq + hq)*S_ + (size_t)n*CHUNK) * DKd;
        size_t kv_off = (((size_t)b*HVv + h )*S_ + (size_t)n*CHUNK) * DKd;
        size_t gb_off = ((size_t)b*HVv + h)*S_ + (size_t)n*CHUNK;

        __syncthreads();
        for (int idx = tid; idx < 2048; idx += 512) {
            int r = idx >> 5, d = (idx & 31) * 4;
            float4 kc = *(const float4*)&g_kcd[kv_off + (size_t)r*128 + d];
            float4 qv = *(const float4*)&g_q  [qk_off + (size_t)r*128 + d];
            float4 kv = *(const float4*)&g_k  [qk_off + (size_t)r*128 + d];
            *(__half2*)&kcd16[r*SH6 + d]     = __floats2half2_rn(-kc.x, -kc.y);
            *(__half2*)&kcd16[r*SH6 + d + 2] = __floats2half2_rn(-kc.z, -kc.w);
            *(__half2*)&q16[r*SH6 + d]       = __floats2half2_rn(qv.x, qv.y);
            *(__half2*)&q16[r*SH6 + d + 2]   = __floats2half2_rn(qv.z, qv.w);
            kT16[(d+0)*SH7 + r] = __float2half_rn(kv.x);
            kT16[(d+1)*SH7 + r] = __float2half_rn(kv.y);
            kT16[(d+2)*SH7 + r] = __float2half_rn(kv.z);
            kT16[(d+3)*SH7 + r] = __float2half_rn(kv.w);
        }
        for (int idx = tid; idx < 1024; idx += 512) {
            int c = idx >> 4, j = (idx & 15) * 4;
            float4 av = *(const float4*)&g_attn[gb_off*CHUNK + (size_t)c*64 + j];
            *(__half2*)&at16[c*SH7 + j]     = __floats2half2_rn(av.x, av.y);
            *(__half2*)&at16[c*SH7 + j + 2] = __floats2half2_rn(av.z, av.w);
        }
        if (tid < 64) {
            float gv = g_gc[gb_off + tid];
            float gl = g_gc[gb_off + 63];
            eg_s[tid] = expf(gv);
            ek_s[tid] = expf(gl - gv);
        }
        __syncthreads();

        // ---- M1: vnew[c,dv] = vadj + (-kcd) @ state ----
        float c0[4], c1[4];
        {
            size_t vb = kv_off + (size_t)(mW + rr)*128 + dvt*64 + nW + cc;
            float2 t;
            t = *(const float2*)&g_vadj[vb];              c0[0]=t.x; c0[1]=t.y;
            t = *(const float2*)&g_vadj[vb + 8*128];      c0[2]=t.x; c0[3]=t.y;
            t = *(const float2*)&g_vadj[vb + 8];          c1[0]=t.x; c1[1]=t.y;
            t = *(const float2*)&g_vadj[vb + 8*128 + 8];  c1[2]=t.x; c1[3]=t.y;
        }
#pragma unroll
        for (int kt = 0; kt < 8; kt++) {
            uint32_t af[4], bf[4];
            ldmx4(af, aKCD + 2u*(kt*16));
            ldmx4(bf, bST  + 2u*(kt*16));
            mma_f16(c0, af, bf);
            mma_f16(c1, af, bf + 2);
        }
        {
            int cr0 = mW + rr, cr1 = mW + rr + 8;
            int d0 = nW + cc, d1 = nW + 8 + cc;
            float e0 = ek_s[cr0], e1 = ek_s[cr1];
            vnT16[(d0  )*SH7 + cr0] = __float2half_rn(c0[0]);
            vnT16[(d0+1)*SH7 + cr0] = __float2half_rn(c0[1]);
            vnT16[(d0  )*SH7 + cr1] = __float2half_rn(c0[2]);
            vnT16[(d0+1)*SH7 + cr1] = __float2half_rn(c0[3]);
            vnT16[(d1  )*SH7 + cr0] = __float2half_rn(c1[0]);
            vnT16[(d1+1)*SH7 + cr0] = __float2half_rn(c1[1]);
            vnT16[(d1  )*SH7 + cr1] = __float2half_rn(c1[2]);
            vnT16[(d1+1)*SH7 + cr1] = __float2half_rn(c1[3]);
            vkT16[(d0  )*SH7 + cr0] = __float2half_rn(c0[0]*e0);
            vkT16[(d0+1)*SH7 + cr0] = __float2half_rn(c0[1]*e0);
            vkT16[(d0  )*SH7 + cr1] = __float2half_rn(c0[2]*e1);
            vkT16[(d0+1)*SH7 + cr1] = __float2half_rn(c0[3]*e1);
            vkT16[(d1  )*SH7 + cr0] = __float2half_rn(c1[0]*e0);
            vkT16[(d1+1)*SH7 + cr0] = __float2half_rn(c1[1]*e0);
            vkT16[(d1  )*SH7 + cr1] = __float2half_rn(c1[2]*e1);
            vkT16[(d1+1)*SH7 + cr1] = __float2half_rn(c1[3]*e1);
        }
        __syncthreads();

        // ---- M2: o = eg[c]*(q@state) + attn@vnew ----
        float o0[4] = {0,0,0,0}, o1[4] = {0,0,0,0};
#pragma unroll
        for (int kt = 0; kt < 8; kt++) {
            uint32_t af[4], bf[4];
            ldmx4(af, aQ  + 2u*(kt*16));
            ldmx4(bf, bST + 2u*(kt*16));
            mma_f16(o0, af, bf);
            mma_f16(o1, af, bf + 2);
        }
        {
            float e0 = eg_s[mW + rr], e1 = eg_s[mW + rr + 8];
            o0[0]*=e0; o0[1]*=e0; o0[2]*=e1; o0[3]*=e1;
            o1[0]*=e0; o1[1]*=e0; o1[2]*=e1; o1[3]*=e1;
        }
#pragma unroll
        for (int kt = 0; kt < 4; kt++) {
            uint32_t af[4], bf[4];
            ldmx4(af, aAT + 2u*(kt*16));
            ldmx4(bf, bVN + 2u*(kt*16));
            mma_f16(o0, af, bf);
            mma_f16(o1, af, bf + 2);
        }
        {
            size_t ob = ((size_t)b*S_ + (size_t)n*CHUNK + mW + rr)*VALUE_DIM
                      + (size_t)h*DVd + dvt*64 + nW + cc;
            *(float2*)&g_o[ob]                       = make_float2(o0[0], o0[1]);
            *(float2*)&g_o[ob + 8*(size_t)VALUE_DIM] = make_float2(o0[2], o0[3]);
            *(float2*)&g_o[ob + 8]                   = make_float2(o1[0], o1[1]);
            *(float2*)&g_o[ob + 8*(size_t)VALUE_DIM + 8] = make_float2(o1[2], o1[3]);
        }
        __syncthreads();

        // ---- M3: state_T[dv,dk] = egl*state_T + vek^T @ k ----
        float egl = eg_s[63];
#pragma unroll
        for (int i = 0; i < 2; i++) {
            int t = wid * 2 + i;
            int dv0 = (t >> 3) * 16, dk0 = (t & 7) * 16;
            float s0[4], s1[4];
            float* sp  = &stT[(dv0 + rr)*STF + dk0 + cc];
            float* sp8 = &stT[(dv0 + rr + 8)*STF + dk0 + cc];
            s0[0] = sp[0]*egl;  s0[1] = sp[1]*egl;
            s1[0] = sp[8]*egl;  s1[1] = sp[9]*egl;
            s0[2] = sp8[0]*egl; s0[3] = sp8[1]*egl;
            s1[2] = sp8[8]*egl; s1[3] = sp8[9]*egl;
            uint32_t aV = smem_u32(vkT16) + 2u*((dv0 + (g&1)*8 + lr)*SH7 + (g>>1)*8);
            uint32_t bK = smem_u32(kT16)  + 2u*((dk0 + (g>>1)*8 + lr)*SH7 + (g&1)*8);
#pragma unroll
            for (int kt = 0; kt < 4; kt++) {
                uint32_t af[4], bf[4];
                ldmx4(af, aV + 2u*(kt*16));
                ldmx4(bf, bK + 2u*(kt*16));
                mma_f16(s0, af, bf);
                mma_f16(s1, af, bf + 2);
            }
            sp[0]=s0[0];  sp[1]=s0[1];  sp[8]=s1[0];  sp[9]=s1[1];
            sp8[0]=s0[2]; sp8[1]=s0[3]; sp8[8]=s1[2]; sp8[9]=s1[3];
            *(__half2*)&st16[(dv0+rr)*SH6 + dk0 + cc]       = __floats2half2_rn(s0[0], s0[1]);
            *(__half2*)&st16[(dv0+rr)*SH6 + dk0 + 8 + cc]   = __floats2half2_rn(s1[0], s1[1]);
            *(__half2*)&st16[(dv0+rr+8)*SH6 + dk0 + cc]     = __floats2half2_rn(s0[2], s0[3]);
            *(__half2*)&st16[(dv0+rr+8)*SH6 + dk0 + 8 + cc] = __floats2half2_rn(s1[2], s1[3]);
        }
    }
}

// -------- gated RMSNorm -> fp16 directly into GEMM2 A buffer --------
__global__ void gated_norm(const float* __restrict__ nw) {
    int bs = blockIdx.x;
    int warp = threadIdx.x >> 5, lane = threadIdx.x & 31;
    for (int h = warp; h < HVv; h += 8) {
        size_t off = (size_t)bs * VALUE_DIM + (size_t)h * DVd;
        float4 v = ((float4*)(g_o + off))[lane];
        float ss = v.x*v.x + v.y*v.y + v.z*v.z + v.w*v.w;
#pragma unroll
        for (int o = 16; o; o >>= 1) ss += __shfl_xor_sync(~0u, ss, o);
        float r = rsqrtf(ss / 128.f + 1e-6f);
        size_t zoff = (size_t)bs * QKVZ_N + 2*KEY_DIM + VALUE_DIM + (size_t)h * DVd;
        float4 z = ((const float4*)(g_qkvz + zoff))[lane];
        float4 w = ((const float4*)nw)[lane];
        float r0 = v.x * r * w.x * (z.x / (1.f + expf(-z.x)));
        float r1 = v.y * r * w.y * (z.y / (1.f + expf(-z.y)));
        float r2 = v.z * r * w.z * (z.z / (1.f + expf(-z.z)));
        float r3 = v.w * r * w.w * (z.w / (1.f + expf(-z.w)));
        __half2 h0 = __floats2half2_rn(r0, r1);
        __half2 h1 = __floats2half2_rn(r2, r3);
        uint2 hv; hv.x = *(uint32_t*)&h0; hv.y = *(uint32_t*)&h1;
        ((uint2*)(g_r + off))[lane] = hv;
    }
}

// ---------------- launcher (single stream) ----------------
extern "C" void kernel_launch(void* const* d_in, const int* in_sizes, int n_in,
                              void* d_out, int out_size) {
    const float* hidden = (const float*)d_in[0];
    const float* Wqkvz  = (const float*)d_in[1];
    const float* Wba    = (const float*)d_in[2];
    const float* convw  = (const float*)d_in[3];
    const float* dtb    = (const float*)d_in[4];
    const float* Alog   = (const float*)d_in[5];
    const float* nw     = (const float*)d_in[6];
    const float* Wout   = (const float*)d_in[7];
    float* out = (float*)d_out;

    float *qkvz_p;
    __half *p_p, *r_p;
    cudaGetSymbolAddress((void**)&qkvz_p, g_qkvz);
    cudaGetSymbolAddress((void**)&p_p, g_p);
    cudaGetSymbolAddress((void**)&r_p, g_r);

    const int SMEM3 = (2*64*SW + 3*4096 + 64*65) * 4 + 2*64*SH6 * 2;   // 168192
    const int SMEM4 = 64*STF*4 + (3*64*SH6 + 128*SH7 + 3*64*SH7) * 2;  // 132096
    const int SMEM_MM = NSTG * STG1 * 2;
    cudaFuncSetAttribute(chunk_prep, cudaFuncAttributeMaxDynamicSharedMemorySize, SMEM3);
    cudaFuncSetAttribute(scan_kernel, cudaFuncAttributeMaxDynamicSharedMemorySize, SMEM4);
    cudaFuncSetAttribute(mmgemm, cudaFuncAttributeMaxDynamicSharedMemorySize, SMEM_MM);

    // --- GEMM1: qkvz = hidden @ W_qkvz ---
    cvt_h<<<(BSz*(size_t)HID)/1024, 256>>>(hidden, p_p);
    cvt_T<<<dim3(QKVZ_N/32, HID/32), dim3(32,8)>>>(Wqkvz, r_p, HID, QKVZ_N);
    mmgemm<<<dim3(BSz/128, QKVZ_N/128), 256, SMEM_MM>>>(p_p, r_p, qkvz_p, BSz, QKVZ_N, HID);

    // --- BA projection (split-K; reduce fused into conv_gate) ---
    gemm_ba_part<<<dim3(BSz/64, 8), 256>>>(hidden, Wba);

    // --- conv + gates, chunk prep (HMMA dots, dedup head pairs), scan (HMMA), norm ---
    conv_gate<<<BSz, 256>>>(convw, dtb, Alog);
    chunk_prep<<<B_*HKq*NCH, 256, SMEM3>>>();
    scan_kernel<<<dim3(B_*HVv, 2), 512, SMEM4>>>();
    gated_norm<<<BSz, 256>>>(nw);

    // --- GEMM2: out = o @ W_out (A written fp16 by gated_norm) ---
    cvt_T<<<dim3(HID/32, VALUE_DIM/32), dim3(32,8)>>>(Wout, p_p, VALUE_DIM, HID);
    mmgemm<<<dim3(BSz/128, HID/128), 256, SMEM_MM>>>(r_p, p_p, out, BSz, HID, VALUE_DIM);
}

// round 14
// speedup vs baseline: 1.6685x; 1.1183x over previous
#include <cuda_runtime.h>
#include <cuda_bf16.h>
#include <cuda_fp16.h>
#include <math.h>
#include <stdint.h>

// ---------------- problem constants ----------------
#define B_   2
#define S_   2048
#define HID  2048
#define HKq  16
#define HVv  32
#define DKd  128
#define DVd  128
#define KC   4
#define CHUNK 64
#define NCH  (S_/CHUNK)          // 32
#define KEY_DIM 2048
#define VALUE_DIM 4096
#define CONV_DIM 8192
#define QKVZ_N 12288
#define BSz  (B_*S_)             // 4096
#define QSCALE 0.08838834764831845f   // DK^-0.5
#define SW 132                   // float4-aligned, conflict-free smem row stride
#define STF 132                  // state_T fp32 row stride (floats)
#define SH6 136                  // fp16 stride for [*][128] tiles
#define SH7 72                   // fp16 stride for [*][64] tiles

// ---------------- scratch (static device memory; no allocations) ------------
__device__ float g_qkvz[(size_t)BSz*QKVZ_N];               // [BS,12288] q|k|v|z
__device__ float g_ba[(size_t)BSz*64];
__device__ float g_q[(size_t)B_*HKq*S_*DKd];
__device__ float g_k[(size_t)B_*HKq*S_*DKd];
__device__ float g_v[(size_t)B_*HVv*S_*DVd];
__device__ float g_g[(size_t)B_*HVv*S_];
__device__ float g_beta[(size_t)B_*HVv*S_];
__device__ float g_gc[(size_t)B_*HVv*S_];
__device__ float g_vadj[(size_t)B_*HVv*S_*DVd];
__device__ float g_kcd[(size_t)B_*HVv*S_*DKd];
__device__ float g_attn[(size_t)B_*HVv*S_*CHUNK];
__device__ float g_o[(size_t)BSz*VALUE_DIM];

// fp16 operand buffers
__device__ __half g_p [(size_t)8388608];    // A1 (hidden) / B2t (Wout^T)
__device__ __half g_r [(size_t)25165824];   // B1t (Wqkvz^T) ; later A2 (gated_norm out)
__device__ __half g_wba[(size_t)64*2048];   // W_ba^T fp16

__device__ __forceinline__ uint32_t smem_u32(const void* p) {
    uint32_t a;
    asm("{ .reg .u64 t; cvta.to.shared.u64 t, %1; cvt.u32.u64 %0, t; }" : "=r"(a) : "l"(p));
    return a;
}

// ---------------- fp32 -> fp16 (elementwise, float4) ----------------
__global__ void cvt_h(const float* __restrict__ X, __half* __restrict__ H) {
    size_t i = ((size_t)blockIdx.x * 256 + threadIdx.x) * 4;
    float4 v = *(const float4*)&X[i];
    __half2 h0 = __floats2half2_rn(v.x, v.y);
    __half2 h1 = __floats2half2_rn(v.z, v.w);
    uint2 hv;
    hv.x = *(uint32_t*)&h0; hv.y = *(uint32_t*)&h1;
    *(uint2*)&H[i] = hv;
}

// ---------------- fp32 [K,N] -> fp16 [N,K] transpose ----------------
__global__ void cvt_T(const float* __restrict__ W, __half* __restrict__ Ht, int K, int N) {
    __shared__ float tile[32][33];
    int n0 = blockIdx.x * 32, k0 = blockIdx.y * 32;
    int tx = threadIdx.x, ty = threadIdx.y;   // 32 x 8
#pragma unroll
    for (int j = 0; j < 32; j += 8)
        tile[ty + j][tx] = W[(size_t)(k0 + ty + j) * N + n0 + tx];
    __syncthreads();
#pragma unroll
    for (int j = 0; j < 32; j += 8)
        Ht[(size_t)(n0 + ty + j) * K + k0 + tx] = __float2half_rn(tile[tx][ty + j]);
}

// ============ fp16 HMMA GEMM: C[M,N] = A[M,K] @ Bt[N,K]^T (fp32 accum) ============
#define PSH 40
#define TEN2 (128*PSH)
#define STG1 (2*TEN2)
#define NSTG 4

__device__ __forceinline__ void mma_f16(float* c, const uint32_t* a, const uint32_t* b) {
    asm volatile("mma.sync.aligned.m16n8k16.row.col.f32.f16.f16.f32 "
                 "{%0,%1,%2,%3}, {%4,%5,%6,%7}, {%8,%9}, {%0,%1,%2,%3};"
                 : "+f"(c[0]), "+f"(c[1]), "+f"(c[2]), "+f"(c[3])
                 : "r"(a[0]), "r"(a[1]), "r"(a[2]), "r"(a[3]), "r"(b[0]), "r"(b[1]));
}
__device__ __forceinline__ void ldmx4(uint32_t* r, uint32_t addr) {
    asm volatile("ldmatrix.sync.aligned.m8n8.x4.shared.b16 {%0,%1,%2,%3}, [%4];"
                 : "=r"(r[0]), "=r"(r[1]), "=r"(r[2]), "=r"(r[3]) : "r"(addr));
}

__device__ __forceinline__ void stage_load(uint32_t sbase_b, int stage,
    const __half* a0, const __half* b0, int K, int kt, int tid)
{
    const __half* gp[2] = {a0, b0};
    uint32_t st_b = sbase_b + (uint32_t)stage * (STG1 * 2);
#pragma unroll
    for (int t = 0; t < 2; t++) {
        uint32_t tb = st_b + (uint32_t)t * (TEN2 * 2);
#pragma unroll
        for (int j = 0; j < 2; j++) {
            int idx = j * 256 + tid;
            int row = idx >> 2, c16 = idx & 3;
            uint32_t sa = tb + (uint32_t)(row * (PSH*2) + c16 * 16);
            const void* ga = gp[t] + (size_t)row * K + (size_t)kt * 32 + c16 * 8;
            asm volatile("cp.async.cg.shared.global [%0], [%1], 16;" :: "r"(sa), "l"(ga));
        }
    }
    asm volatile("cp.async.commit_group;" ::: "memory");
}

__global__ void __launch_bounds__(256, 2) mmgemm(
    const __half* __restrict__ Ah, const __half* __restrict__ Bh,
    float* __restrict__ C, int M, int N, int K)
{
    extern __shared__ __half smem[];
    uint32_t sbase = smem_u32(smem);
    int tid = threadIdx.x, lane = tid & 31, wid = tid >> 5;
    int warpM = wid >> 2, warpN = wid & 3;
    int bm = blockIdx.x, bn = blockIdx.y;
    const int T = K >> 5;

    const __half* a0 = Ah + (size_t)bm * 128 * K;
    const __half* b0 = Bh + (size_t)bn * 128 * K;

    int g = lane >> 3, lr = lane & 7;
    uint32_t aoff = (uint32_t)((warpM*64 + (g&1)*8 + lr) * PSH + (g>>1)*8);
    uint32_t boff = (uint32_t)((warpN*32 + (g>>1)*8 + lr) * PSH + (g&1)*8);

    float acc[4][4][4];
#pragma unroll
    for (int i = 0; i < 4; i++)
#pragma unroll
        for (int j = 0; j < 4; j++)
#pragma unroll
            for (int r = 0; r < 4; r++) acc[i][j][r] = 0.f;

    stage_load(sbase, 0, a0, b0, K, 0, tid);
    stage_load(sbase, 1, a0, b0, K, 1, tid);
    stage_load(sbase, 2, a0, b0, K, 2, tid);

    for (int kt = 0; kt < T; kt++) {
        int rem = T - 1 - kt;
        if (rem >= 2)      asm volatile("cp.async.wait_group 2;" ::: "memory");
        else if (rem == 1) asm volatile("cp.async.wait_group 1;" ::: "memory");
        else               asm volatile("cp.async.wait_group 0;" ::: "memory");
        __syncthreads();
        if (kt + 3 < T) stage_load(sbase, (kt + 3) % NSTG, a0, b0, K, kt + 3, tid);

        uint32_t st = sbase + (uint32_t)(kt % NSTG) * (STG1 * 2);
        uint32_t sA = st, sB = st + TEN2*2;
#pragma unroll
        for (int ks = 0; ks < 2; ks++) {
            int kk = ks * 16;
            uint32_t ah[4][4], bh[4][2];
#pragma unroll
            for (int mi = 0; mi < 4; mi++)
                ldmx4(ah[mi], sA + (aoff + mi*16*PSH + kk) * 2);
#pragma unroll
            for (int p = 0; p < 2; p++) {
                uint32_t rh[4];
                ldmx4(rh, sB + (boff + p*16*PSH + kk) * 2);
                bh[2*p][0] = rh[0]; bh[2*p][1] = rh[1];
                bh[2*p+1][0] = rh[2]; bh[2*p+1][1] = rh[3];
            }
#pragma unroll
            for (int mi = 0; mi < 4; mi++)
#pragma unroll
                for (int ni = 0; ni < 4; ni++)
                    mma_f16(acc[mi][ni], ah[mi], bh[ni]);
        }
        __syncthreads();
    }

    int rr = lane >> 2, cc = (lane & 3) * 2;
#pragma unroll
    for (int mi = 0; mi < 4; mi++) {
        int row0 = bm * 128 + warpM * 64 + mi * 16 + rr;
#pragma unroll
        for (int ni = 0; ni < 4; ni++) {
            int col = bn * 128 + warpN * 32 + ni * 8 + cc;
            float2 v0 = make_float2(acc[mi][ni][0], acc[mi][ni][1]);
            float2 v1 = make_float2(acc[mi][ni][2], acc[mi][ni][3]);
            *(float2*)&C[(size_t)row0 * N + col]       = v0;
            *(float2*)&C[(size_t)(row0 + 8) * N + col] = v1;
        }
    }
}

// ------------- BA projection, HMMA: g_ba[BSz,64] = hidden_fp16 @ Wba^T -------------
__global__ void __launch_bounds__(256) gemm_ba_h(const __half* __restrict__ A) {
    __shared__ __half As[2][32*SH7];
    __shared__ __half Bs[2][64*SH7];
    int tid = threadIdx.x, lane = tid & 31, wid = tid >> 5;
    int bm = blockIdx.x;
    int wm = wid >> 2, wn = wid & 3;        // 2 x 4 warps (m16 x n16)
    int g = lane >> 3, lr = lane & 7;
    const __half* Ab = A + (size_t)bm * 32 * 2048;

    uint32_t aoff = (uint32_t)((wm*16 + (g&1)*8 + lr) * SH7 + (g>>1)*8);
    uint32_t boff = (uint32_t)((wn*16 + (g>>1)*8 + lr) * SH7 + (g&1)*8);
    uint32_t asA[2] = { smem_u32(As[0]), smem_u32(As[1]) };
    uint32_t asB[2] = { smem_u32(Bs[0]), smem_u32(Bs[1]) };

    float acc[2][4] = {};

    // stage loader: BK=64 halfs
    auto ld = [&](int st, int kt) {
        {
            int row = tid >> 3, ch = tid & 7;   // 32 rows x 8 chunks
            uint32_t dst = asA[st] + (uint32_t)(row*SH7 + ch*8) * 2;
            const void* src = Ab + (size_t)row*2048 + kt*64 + ch*8;
            asm volatile("cp.async.cg.shared.global [%0], [%1], 16;" :: "r"(dst), "l"(src));
        }
#pragma unroll
        for (int j = 0; j < 2; j++) {
            int idx = j*256 + tid;
            int row = idx >> 3, ch = idx & 7;   // 64 rows x 8 chunks
            uint32_t dst = asB[st] + (uint32_t)(row*SH7 + ch*8) * 2;
            const void* src = g_wba + (size_t)row*2048 + kt*64 + ch*8;
            asm volatile("cp.async.cg.shared.global [%0], [%1], 16;" :: "r"(dst), "l"(src));
        }
        asm volatile("cp.async.commit_group;" ::: "memory");
    };

    ld(0, 0);
    for (int kt = 0; kt < 32; kt++) {
        if (kt + 1 < 32) {
            ld((kt + 1) & 1, kt + 1);
            asm volatile("cp.async.wait_group 1;" ::: "memory");
        } else {
            asm volatile("cp.async.wait_group 0;" ::: "memory");
        }
        __syncthreads();
        int st = kt & 1;
#pragma unroll
        for (int ks = 0; ks < 4; ks++) {
            uint32_t af[4], bf[4];
            ldmx4(af, asA[st] + (aoff + ks*16) * 2);
            ldmx4(bf, asB[st] + (boff + ks*16) * 2);
            mma_f16(acc[0], af, bf);
            mma_f16(acc[1], af, bf + 2);
        }
        __syncthreads();
    }

    int rr = lane >> 2, cc = (lane & 3) * 2;
    int row0 = bm * 32 + wm * 16 + rr;
#pragma unroll
    for (int ni = 0; ni < 2; ni++) {
        int col = wn * 16 + ni * 8 + cc;
        *(float2*)&g_ba[(size_t)row0 * 64 + col]       = make_float2(acc[ni][0], acc[ni][1]);
        *(float2*)&g_ba[(size_t)(row0 + 8) * 64 + col] = make_float2(acc[ni][2], acc[ni][3]);
    }
}

// -------- conv + silu + l2norm + head transpose + gates (float4-vectorized) --------
__global__ void conv_gate(const float* __restrict__ cw, const float* __restrict__ dtb,
                          const float* __restrict__ Alog) {
    int bs = blockIdx.x;
    int b = bs / S_, s = bs % S_;
    int tid = threadIdx.x;
    __shared__ float cs[CONV_DIM];
    __shared__ float hsum[32];
    const float* base = g_qkvz + (size_t)bs * QKVZ_N;
    const float4* cw4 = (const float4*)cw;

    for (int c4 = tid; c4 < CONV_DIM / 4; c4 += 256) {
        int c = c4 * 4;
        float4 w0 = cw4[c + 0], w1 = cw4[c + 1], w2 = cw4[c + 2], w3 = cw4[c + 3];
        float4 x3 = *(const float4*)&base[c];
        float4 r;
        r.x = x3.x * w0.w; r.y = x3.y * w1.w; r.z = x3.z * w2.w; r.w = x3.w * w3.w;
        if (s >= 1) {
            float4 x2 = *(const float4*)&base[c - (size_t)QKVZ_N];
            r.x += x2.x * w0.z; r.y += x2.y * w1.z; r.z += x2.z * w2.z; r.w += x2.w * w3.z;
        }
        if (s >= 2) {
            float4 x1 = *(const float4*)&base[c - (size_t)2*QKVZ_N];
            r.x += x1.x * w0.y; r.y += x1.y * w1.y; r.z += x1.z * w2.y; r.w += x1.w * w3.y;
        }
        if (s >= 3) {
            float4 x0 = *(const float4*)&base[c - (size_t)3*QKVZ_N];
            r.x += x0.x * w0.x; r.y += x0.y * w1.x; r.z += x0.z * w2.x; r.w += x0.w * w3.x;
        }
        r.x = r.x / (1.f + __expf(-r.x));
        r.y = r.y / (1.f + __expf(-r.y));
        r.z = r.z / (1.f + __expf(-r.z));
        r.w = r.w / (1.f + __expf(-r.w));
        *(float4*)&cs[c] = r;
    }
    __syncthreads();
    int warp = tid >> 5, lane = tid & 31;
    for (int h = warp; h < 32; h += 8) {
        float ss = 0.f;
        for (int d = lane; d < 128; d += 32) { float v = cs[h*128 + d]; ss += v * v; }
#pragma unroll
        for (int o = 16; o; o >>= 1) ss += __shfl_xor_sync(~0u, ss, o);
        if (!lane) hsum[h] = rsqrtf(ss + 1e-6f);
    }
    __syncthreads();
    for (int c4 = tid; c4 < KEY_DIM / 4; c4 += 256) {
        int c = c4 * 4;
        int h = c >> 7, d = c & 127;
        float sc = hsum[h] * QSCALE;
        float4 v = *(float4*)&cs[c];
        v.x *= sc; v.y *= sc; v.z *= sc; v.w *= sc;
        *(float4*)&g_q[(((size_t)b*HKq + h)*S_ + s)*DKd + d] = v;
    }
    for (int c4 = tid; c4 < KEY_DIM / 4; c4 += 256) {
        int c = c4 * 4;
        int h = c >> 7, d = c & 127;
        float sc = hsum[16 + h];
        float4 v = *(float4*)&cs[KEY_DIM + c];
        v.x *= sc; v.y *= sc; v.z *= sc; v.w *= sc;
        *(float4*)&g_k[(((size_t)b*HKq + h)*S_ + s)*DKd + d] = v;
    }
    for (int c4 = tid; c4 < VALUE_DIM / 4; c4 += 256) {
        int c = c4 * 4;
        int h = c >> 7, d = c & 127;
        float4 v = *(float4*)&cs[2*KEY_DIM + c];
        *(float4*)&g_v[(((size_t)b*HVv + h)*S_ + s)*DVd + d] = v;
    }
    if (tid < 64) {
        float bb = g_ba[(size_t)bs * 64 + tid];
        if (tid < 32) {
            g_beta[((size_t)b*HVv + tid)*S_ + s] = 1.f / (1.f + expf(-bb));
        } else {
            int h = tid - 32;
            float a = bb + dtb[h];
            float sp = (a > 20.f) ? a : log1pf(expf(a));
            g_g[((size_t)b*HVv + h)*S_ + s] = -expf(Alog[h]) * sp;
        }
    }
}

// ======== chunk_prep: grid (b*hq*n)=1024; HMMA dots; dual-head T-solve ========
__global__ void __launch_bounds__(256, 1) chunk_prep() {
    extern __shared__ char smraw[];
    float* k_s   = (float*)smraw;              // [64][SW]
    float* vb_s  = k_s + 64*SW;                // [64][SW]
    float* dotsA = vb_s + 64*SW;               // [64*64] k.k
    float* dotsQ = dotsA + 4096;               // [64*64] q.k
    float* A2    = dotsQ + 4096;               // [2][64*64]
    float* T2    = A2 + 8192;                  // [2][64*65]
    __half* k16  = (__half*)(T2 + 8320);       // [64][SH6]
    __half* q16  = k16 + 64*SH6;               // [64][SH6]
    __shared__ float gc2[2][64], beta2[2][64], kbe2[2][64];

    int blk = blockIdx.x;
    int n = blk & 31, hq = (blk >> 5) & 15, b = blk >> 9;
    int tid = threadIdx.x, lane = tid & 31, wid = tid >> 5;

    size_t qk_off = (((size_t)b*HKq + hq)*S_ + (size_t)n*CHUNK) * DKd;

    // load q,k once (fp32 k for T products, fp16 q/k for dots)
    for (int idx = tid; idx < 2048; idx += 256) {
        int r = idx >> 5, d = (idx & 31) * 4;
        float4 qv = *(const float4*)&g_q[qk_off + (size_t)r*128 + d];
        float4 kv = *(const float4*)&g_k[qk_off + (size_t)r*128 + d];
        *(float4*)&k_s[r*SW + d] = kv;
        *(__half2*)&q16[r*SH6 + d]     = __floats2half2_rn(qv.x, qv.y);
        *(__half2*)&q16[r*SH6 + d + 2] = __floats2half2_rn(qv.z, qv.w);
        *(__half2*)&k16[r*SH6 + d]     = __floats2half2_rn(kv.x, kv.y);
        *(__half2*)&k16[r*SH6 + d + 2] = __floats2half2_rn(kv.z, kv.w);
    }
    // gates both heads
    if (tid < 128) {
        int hh = tid >> 6, i = tid & 63;
        size_t gb = ((size_t)b*HVv + hq*2 + hh)*S_ + (size_t)n*CHUNK;
        gc2[hh][i] = g_g[gb + i];
        beta2[hh][i] = g_beta[gb + i];
    }
    __syncthreads();
    if (tid < 2) {
        float* gcp = gc2[tid];
        for (int i = 1; i < 64; i++) gcp[i] += gcp[i - 1];
    }
    __syncthreads();
    if (tid < 128) {
        int hh = tid >> 6, i = tid & 63;
        size_t gb = ((size_t)b*HVv + hq*2 + hh)*S_ + (size_t)n*CHUNK;
        g_gc[gb + i] = gc2[hh][i];
        kbe2[hh][i] = beta2[hh][i] * expf(gc2[hh][i]);
    }

    // HMMA dots: dotsA = k @ k^T, dotsQ = q @ k^T. Warp grid 4(m16) x 2(n32).
    {
        int mW = (wid >> 1) * 16, nW = (wid & 1) * 32;
        int g = lane >> 3, lr = lane & 7;
        uint32_t aK = smem_u32(k16) + 2u*(uint32_t)((mW + (g&1)*8 + lr)*SH6 + (g>>1)*8);
        uint32_t aQ = smem_u32(q16) + 2u*(uint32_t)((mW + (g&1)*8 + lr)*SH6 + (g>>1)*8);
        uint32_t bK = smem_u32(k16) + 2u*(uint32_t)((nW + (g>>1)*8 + lr)*SH6 + (g&1)*8);
        float accK[4][4], accQ[4][4];
#pragma unroll
        for (int i = 0; i < 4; i++)
#pragma unroll
            for (int r = 0; r < 4; r++) { accK[i][r] = 0.f; accQ[i][r] = 0.f; }
#pragma unroll
        for (int kt = 0; kt < 8; kt++) {
            uint32_t afk[4], afq[4], b0[4], b1[4];
            ldmx4(afk, aK + 2u*(kt*16));
            ldmx4(afq, aQ + 2u*(kt*16));
            ldmx4(b0, bK + 2u*(kt*16));
            ldmx4(b1, bK + 2u*(16*SH6 + kt*16));
            mma_f16(accK[0], afk, b0); mma_f16(accK[1], afk, b0 + 2);
            mma_f16(accK[2], afk, b1); mma_f16(accK[3], afk, b1 + 2);
            mma_f16(accQ[0], afq, b0); mma_f16(accQ[1], afq, b0 + 2);
            mma_f16(accQ[2], afq, b1); mma_f16(accQ[3], afq, b1 + 2);
        }
        int rr = lane >> 2, cc = (lane & 3) * 2;
#pragma unroll
        for (int ni = 0; ni < 4; ni++) {
            int j = nW + ni*8 + cc;
            int c0r = mW + rr;
            *(float2*)&dotsA[c0r*64 + j]     = make_float2(accK[ni][0], accK[ni][1]);
            *(float2*)&dotsA[(c0r+8)*64 + j] = make_float2(accK[ni][2], accK[ni][3]);
            *(float2*)&dotsQ[c0r*64 + j]     = make_float2(accQ[ni][0], accQ[ni][1]);
            *(float2*)&dotsQ[(c0r+8)*64 + j] = make_float2(accQ[ni][2], accQ[ni][3]);
        }
    }
    __syncthreads();

    // A + attn for BOTH heads
    for (int idx = tid; idx < 8192; idx += 256) {
        int hh = idx >> 12, i = idx & 4095;
        int c = i >> 6, j = i & 63;
        float e = __expf(gc2[hh][c] - gc2[hh][j]);
        A2[hh*4096 + i] = (j < c) ? dotsA[i] * beta2[hh][c] * e : 0.f;
        size_t at_off = (((size_t)b*HVv + hq*2 + hh)*S_ + (size_t)n*CHUNK) * CHUNK;
        g_attn[at_off + i] = (j <= c) ? dotsQ[i] * e : 0.f;
    }
    __syncthreads();

    // T-solve BOTH heads concurrently (columns independent)
    if (tid < 128) {
        int hh = tid >> 6, col = tid & 63;
        float* A_s = A2 + hh*4096;
        float* T_s = T2 + hh*4160;
        for (int c = 0; c < 64; c++) {
            float ssum = (c == col) ? 1.f : 0.f;
            for (int j = col; j < c; j++) ssum -= A_s[c*64 + j] * T_s[j*65 + col];
            T_s[c*65 + col] = (c >= col) ? ssum : 0.f;
        }
    }
    __syncthreads();

    // products per head
#pragma unroll 1
    for (int h2 = 0; h2 < 2; h2++) {
        int h = hq * 2 + h2;
        size_t v_off  = (((size_t)b*HVv + h)*S_ + (size_t)n*CHUNK) * DVd;
        size_t gb_off = ((size_t)b*HVv + h)*S_ + (size_t)n*CHUNK;
        float* T_s = T2 + h2*4160;

        for (int idx = tid; idx < 2048; idx += 256) {
            int r = idx >> 5, d = (idx & 31) * 4;
            float4 vv = *(const float4*)&g_v[v_off + (size_t)r*128 + d];
            float be = beta2[h2][r];
            vv.x *= be; vv.y *= be; vv.z *= be; vv.w *= be;
            *(float4*)&vb_s[r*SW + d] = vv;
        }
        __syncthreads();

        {
            int ct8 = tid >> 5, lane2 = tid & 31;
            int c0 = ct8 * 8, d0 = lane2 * 4;
            float av[8][4] = {}, ak[8][4] = {};
            int jmax = c0 + 8;
            for (int j = 0; j < jmax; j++) {
                float4 vv = *(float4*)&vb_s[j*SW + d0];
                float4 kk = *(float4*)&k_s [j*SW + d0];
                float kb = kbe2[h2][j];
                kk.x *= kb; kk.y *= kb; kk.z *= kb; kk.w *= kb;
#pragma unroll
                for (int ci = 0; ci < 8; ci++) {
                    float t = T_s[(c0+ci)*65 + j];
                    av[ci][0] += t*vv.x; av[ci][1] += t*vv.y; av[ci][2] += t*vv.z; av[ci][3] += t*vv.w;
                    ak[ci][0] += t*kk.x; ak[ci][1] += t*kk.y; ak[ci][2] += t*kk.z; ak[ci][3] += t*kk.w;
                }
            }
            size_t kcd_off = gb_off * DKd;
#pragma unroll
            for (int ci = 0; ci < 8; ci++) {
                *(float4*)&g_vadj[v_off   + (size_t)(c0+ci)*128 + d0] =
                    make_float4(av[ci][0], av[ci][1], av[ci][2], av[ci][3]);
                *(float4*)&g_kcd [kcd_off + (size_t)(c0+ci)*128 + d0] =
                    make_float4(ak[ci][0], ak[ci][1], ak[ci][2], ak[ci][3]);
            }
        }
        __syncthreads();
    }
}

// ======== HMMA scan: state_T fp32 [dv][dk]; per-chunk fp16 operand tiles ========
__global__ void __launch_bounds__(512, 1) scan_kernel() {
    extern __shared__ char smraw[];
    float*  stT  = (float*)smraw;                 // [64][STF]
    __half* st16 = (__half*)(stT + 64*STF);       // [64][SH6]
    __half* kcd16= st16 + 64*SH6;                 // [64][SH6]
    __half* q16  = kcd16 + 64*SH6;                // [64][SH6]
    __half* kT16 = q16 + 64*SH6;                  // [128][SH7]
    __half* at16 = kT16 + 128*SH7;                // [64][SH7]
    __half* vnT16= at16 + 64*SH7;                 // [64][SH7]
    __half* vkT16= vnT16 + 64*SH7;                // [64][SH7]
    __shared__ float eg_s[64], ek_s[64];

    int bh = blockIdx.x, dvt = blockIdx.y;
    int b = bh >> 5, h = bh & 31, hq = h >> 1;
    int tid = threadIdx.x, lane = tid & 31, wid = tid >> 5;

    int mW = (wid >> 2) * 16;
    int nW = (wid & 3) * 16;
    int g = lane >> 3, lr = lane & 7;
    int rr = lane >> 2, cc = (lane & 3) * 2;

    for (int i = tid; i < 64*STF; i += 512) stT[i] = 0.f;
    for (int i = tid; i < 64*SH6; i += 512) st16[i] = __float2half(0.f);

    uint32_t aKCD = smem_u32(kcd16) + 2u*((mW + (g&1)*8 + lr)*SH6 + (g>>1)*8);
    uint32_t aQ   = smem_u32(q16)   + 2u*((mW + (g&1)*8 + lr)*SH6 + (g>>1)*8);
    uint32_t aAT  = smem_u32(at16)  + 2u*((mW + (g&1)*8 + lr)*SH7 + (g>>1)*8);
    uint32_t bST  = smem_u32(st16)  + 2u*((nW + (g>>1)*8 + lr)*SH6 + (g&1)*8);
    uint32_t bVN  = smem_u32(vnT16) + 2u*((nW + (g>>1)*8 + lr)*SH7 + (g&1)*8);

    for (int n = 0; n < NCH; n++) {
        size_t qk_off = (((size_t)b*HKq + hq)*S_ + (size_t)n*CHUNK) * DKd;
        size_t kv_off = (((size_t)b*HVv + h )*S_ + (size_t)n*CHUNK) * DKd;
        size_t gb_off = ((size_t)b*HVv + h)*S_ + (size_t)n*CHUNK;

        __syncthreads();
        for (int idx = tid; idx < 2048; idx += 512) {
            int r = idx >> 5, d = (idx & 31) * 4;
            float4 kc = *(const float4*)&g_kcd[kv_off + (size_t)r*128 + d];
            float4 qv = *(const float4*)&g_q  [qk_off + (size_t)r*128 + d];
            float4 kv = *(const float4*)&g_k  [qk_off + (size_t)r*128 + d];
            *(__half2*)&kcd16[r*SH6 + d]     = __floats2half2_rn(-kc.x, -kc.y);
            *(__half2*)&kcd16[r*SH6 + d + 2] = __floats2half2_rn(-kc.z, -kc.w);
            *(__half2*)&q16[r*SH6 + d]       = __floats2half2_rn(qv.x, qv.y);
            *(__half2*)&q16[r*SH6 + d + 2]   = __floats2half2_rn(qv.z, qv.w);
            kT16[(d+0)*SH7 + r] = __float2half_rn(kv.x);
            kT16[(d+1)*SH7 + r] = __float2half_rn(kv.y);
            kT16[(d+2)*SH7 + r] = __float2half_rn(kv.z);
            kT16[(d+3)*SH7 + r] = __float2half_rn(kv.w);
        }
        for (int idx = tid; idx < 1024; idx += 512) {
            int c = idx >> 4, j = (idx & 15) * 4;
            float4 av = *(const float4*)&g_attn[gb_off*CHUNK + (size_t)c*64 + j];
            *(__half2*)&at16[c*SH7 + j]     = __floats2half2_rn(av.x, av.y);
            *(__half2*)&at16[c*SH7 + j + 2] = __floats2half2_rn(av.z, av.w);
        }
        if (tid < 64) {
            float gv = g_gc[gb_off + tid];
            float gl = g_gc[gb_off + 63];
            eg_s[tid] = expf(gv);
            ek_s[tid] = expf(gl - gv);
        }
        __syncthreads();

        // ---- M1: vnew[c,dv] = vadj + (-kcd) @ state ----
        float c0[4], c1[4];
        {
            size_t vb = kv_off + (size_t)(mW + rr)*128 + dvt*64 + nW + cc;
            float2 t;
            t = *(const float2*)&g_vadj[vb];              c0[0]=t.x; c0[1]=t.y;
            t = *(const float2*)&g_vadj[vb + 8*128];      c0[2]=t.x; c0[3]=t.y;
            t = *(const float2*)&g_vadj[vb + 8];          c1[0]=t.x; c1[1]=t.y;
            t = *(const float2*)&g_vadj[vb + 8*128 + 8];  c1[2]=t.x; c1[3]=t.y;
        }
#pragma unroll
        for (int kt = 0; kt < 8; kt++) {
            uint32_t af[4], bf[4];
            ldmx4(af, aKCD + 2u*(kt*16));
            ldmx4(bf, bST  + 2u*(kt*16));
            mma_f16(c0, af, bf);
            mma_f16(c1, af, bf + 2);
        }
        {
            int cr0 = mW + rr, cr1 = mW + rr + 8;
            int d0 = nW + cc, d1 = nW + 8 + cc;
            float e0 = ek_s[cr0], e1 = ek_s[cr1];
            vnT16[(d0  )*SH7 + cr0] = __float2half_rn(c0[0]);
            vnT16[(d0+1)*SH7 + cr0] = __float2half_rn(c0[1]);
            vnT16[(d0  )*SH7 + cr1] = __float2half_rn(c0[2]);
            vnT16[(d0+1)*SH7 + cr1] = __float2half_rn(c0[3]);
            vnT16[(d1  )*SH7 + cr0] = __float2half_rn(c1[0]);
            vnT16[(d1+1)*SH7 + cr0] = __float2half_rn(c1[1]);
            vnT16[(d1  )*SH7 + cr1] = __float2half_rn(c1[2]);
            vnT16[(d1+1)*SH7 + cr1] = __float2half_rn(c1[3]);
            vkT16[(d0  )*SH7 + cr0] = __float2half_rn(c0[0]*e0);
            vkT16[(d0+1)*SH7 + cr0] = __float2half_rn(c0[1]*e0);
            vkT16[(d0  )*SH7 + cr1] = __float2half_rn(c0[2]*e1);
            vkT16[(d0+1)*SH7 + cr1] = __float2half_rn(c0[3]*e1);
            vkT16[(d1  )*SH7 + cr0] = __float2half_rn(c1[0]*e0);
            vkT16[(d1+1)*SH7 + cr0] = __float2half_rn(c1[1]*e0);
            vkT16[(d1  )*SH7 + cr1] = __float2half_rn(c1[2]*e1);
            vkT16[(d1+1)*SH7 + cr1] = __float2half_rn(c1[3]*e1);
        }
        __syncthreads();

        // ---- M2: o = eg[c]*(q@state) + attn@vnew ----
        float o0[4] = {0,0,0,0}, o1[4] = {0,0,0,0};
#pragma unroll
        for (int kt = 0; kt < 8; kt++) {
            uint32_t af[4], bf[4];
            ldmx4(af, aQ  + 2u*(kt*16));
            ldmx4(bf, bST + 2u*(kt*16));
            mma_f16(o0, af, bf);
            mma_f16(o1, af, bf + 2);
        }
        {
            float e0 = eg_s[mW + rr], e1 = eg_s[mW + rr + 8];
            o0[0]*=e0; o0[1]*=e0; o0[2]*=e1; o0[3]*=e1;
            o1[0]*=e0; o1[1]*=e0; o1[2]*=e1; o1[3]*=e1;
        }
#pragma unroll
        for (int kt = 0; kt < 4; kt++) {
            uint32_t af[4], bf[4];
            ldmx4(af, aAT + 2u*(kt*16));
            ldmx4(bf, bVN + 2u*(kt*16));
            mma_f16(o0, af, bf);
            mma_f16(o1, af, bf + 2);
        }
        {
            size_t ob = ((size_t)b*S_ + (size_t)n*CHUNK + mW + rr)*VALUE_DIM
                      + (size_t)h*DVd + dvt*64 + nW + cc;
            *(float2*)&g_o[ob]                       = make_float2(o0[0], o0[1]);
            *(float2*)&g_o[ob + 8*(size_t)VALUE_DIM] = make_float2(o0[2], o0[3]);
            *(float2*)&g_o[ob + 8]                   = make_float2(o1[0], o1[1]);
            *(float2*)&g_o[ob + 8*(size_t)VALUE_DIM + 8] = make_float2(o1[2], o1[3]);
        }
        __syncthreads();

        // ---- M3: state_T[dv,dk] = egl*state_T + vek^T @ k ----
        float egl = eg_s[63];
#pragma unroll
        for (int i = 0; i < 2; i++) {
            int t = wid * 2 + i;
            int dv0 = (t >> 3) * 16, dk0 = (t & 7) * 16;
            float s0[4], s1[4];
            float* sp  = &stT[(dv0 + rr)*STF + dk0 + cc];
            float* sp8 = &stT[(dv0 + rr + 8)*STF + dk0 + cc];
            s0[0] = sp[0]*egl;  s0[1] = sp[1]*egl;
            s1[0] = sp[8]*egl;  s1[1] = sp[9]*egl;
            s0[2] = sp8[0]*egl; s0[3] = sp8[1]*egl;
            s1[2] = sp8[8]*egl; s1[3] = sp8[9]*egl;
            uint32_t aV = smem_u32(vkT16) + 2u*((dv0 + (g&1)*8 + lr)*SH7 + (g>>1)*8);
            uint32_t bK = smem_u32(kT16)  + 2u*((dk0 + (g>>1)*8 + lr)*SH7 + (g&1)*8);
#pragma unroll
            for (int kt = 0; kt < 4; kt++) {
                uint32_t af[4], bf[4];
                ldmx4(af, aV + 2u*(kt*16));
                ldmx4(bf, bK + 2u*(kt*16));
                mma_f16(s0, af, bf);
                mma_f16(s1, af, bf + 2);
            }
            sp[0]=s0[0];  sp[1]=s0[1];  sp[8]=s1[0];  sp[9]=s1[1];
            sp8[0]=s0[2]; sp8[1]=s0[3]; sp8[8]=s1[2]; sp8[9]=s1[3];
            *(__half2*)&st16[(dv0+rr)*SH6 + dk0 + cc]       = __floats2half2_rn(s0[0], s0[1]);
            *(__half2*)&st16[(dv0+rr)*SH6 + dk0 + 8 + cc]   = __floats2half2_rn(s1[0], s1[1]);
            *(__half2*)&st16[(dv0+rr+8)*SH6 + dk0 + cc]     = __floats2half2_rn(s0[2], s0[3]);
            *(__half2*)&st16[(dv0+rr+8)*SH6 + dk0 + 8 + cc] = __floats2half2_rn(s1[2], s1[3]);
        }
    }
}

// -------- gated RMSNorm -> fp16 directly into GEMM2 A buffer --------
__global__ void gated_norm(const float* __restrict__ nw) {
    int bs = blockIdx.x;
    int warp = threadIdx.x >> 5, lane = threadIdx.x & 31;
    for (int h = warp; h < HVv; h += 8) {
        size_t off = (size_t)bs * VALUE_DIM + (size_t)h * DVd;
        float4 v = ((float4*)(g_o + off))[lane];
        float ss = v.x*v.x + v.y*v.y + v.z*v.z + v.w*v.w;
#pragma unroll
        for (int o = 16; o; o >>= 1) ss += __shfl_xor_sync(~0u, ss, o);
        float r = rsqrtf(ss / 128.f + 1e-6f);
        size_t zoff = (size_t)bs * QKVZ_N + 2*KEY_DIM + VALUE_DIM + (size_t)h * DVd;
        float4 z = ((const float4*)(g_qkvz + zoff))[lane];
        float4 w = ((const float4*)nw)[lane];
        float r0 = v.x * r * w.x * (z.x / (1.f + expf(-z.x)));
        float r1 = v.y * r * w.y * (z.y / (1.f + expf(-z.y)));
        float r2 = v.z * r * w.z * (z.z / (1.f + expf(-z.z)));
        float r3 = v.w * r * w.w * (z.w / (1.f + expf(-z.w)));
        __half2 h0 = __floats2half2_rn(r0, r1);
        __half2 h1 = __floats2half2_rn(r2, r3);
        uint2 hv; hv.x = *(uint32_t*)&h0; hv.y = *(uint32_t*)&h1;
        ((uint2*)(g_r + off))[lane] = hv;
    }
}

// ---------------- launcher (single stream) ----------------
extern "C" void kernel_launch(void* const* d_in, const int* in_sizes, int n_in,
                              void* d_out, int out_size) {
    const float* hidden = (const float*)d_in[0];
    const float* Wqkvz  = (const float*)d_in[1];
    const float* Wba    = (const float*)d_in[2];
    const float* convw  = (const float*)d_in[3];
    const float* dtb    = (const float*)d_in[4];
    const float* Alog   = (const float*)d_in[5];
    const float* nw     = (const float*)d_in[6];
    const float* Wout   = (const float*)d_in[7];
    float* out = (float*)d_out;

    float *qkvz_p;
    __half *p_p, *r_p, *wba_p;
    cudaGetSymbolAddress((void**)&qkvz_p, g_qkvz);
    cudaGetSymbolAddress((void**)&p_p, g_p);
    cudaGetSymbolAddress((void**)&r_p, g_r);
    cudaGetSymbolAddress((void**)&wba_p, g_wba);

    const int SMEM3 = (2*64*SW + 2*4096 + 2*4096 + 2*64*65) * 4 + 2*64*SH6 * 2; // 201216
    const int SMEM4 = 64*STF*4 + (3*64*SH6 + 128*SH7 + 3*64*SH7) * 2;           // 132096
    const int SMEM_MM = NSTG * STG1 * 2;
    cudaFuncSetAttribute(chunk_prep, cudaFuncAttributeMaxDynamicSharedMemorySize, SMEM3);
    cudaFuncSetAttribute(scan_kernel, cudaFuncAttributeMaxDynamicSharedMemorySize, SMEM4);
    cudaFuncSetAttribute(mmgemm, cudaFuncAttributeMaxDynamicSharedMemorySize, SMEM_MM);

    // --- operand conversions ---
    cvt_h<<<(BSz*(size_t)HID)/1024, 256>>>(hidden, p_p);
    cvt_T<<<dim3(QKVZ_N/32, HID/32), dim3(32,8)>>>(Wqkvz, r_p, HID, QKVZ_N);
    cvt_T<<<dim3(2, HID/32), dim3(32,8)>>>(Wba, wba_p, HID, 64);

    // --- GEMM1: qkvz = hidden @ W_qkvz ---
    mmgemm<<<dim3(BSz/128, QKVZ_N/128), 256, SMEM_MM>>>(p_p, r_p, qkvz_p, BSz, QKVZ_N, HID);

    // --- BA projection (HMMA) ---
    gemm_ba_h<<<BSz/32, 256>>>(p_p);

    // --- conv + gates, chunk prep, scan, norm ---
    conv_gate<<<BSz, 256>>>(convw, dtb, Alog);
    chunk_prep<<<B_*HKq*NCH, 256, SMEM3>>>();
    scan_kernel<<<dim3(B_*HVv, 2), 512, SMEM4>>>();
    gated_norm<<<BSz, 256>>>(nw);

    // --- GEMM2: out = o @ W_out (A written fp16 by gated_norm) ---
    cvt_T<<<dim3(HID/32, VALUE_DIM/32), dim3(32,8)>>>(Wout, p_p, VALUE_DIM, HID);
    mmgemm<<<dim3(BSz/128, HID/128), 256, SMEM_MM>>>(r_p, p_p, out, BSz, HID, VALUE_DIM);
}